// round 12
// baseline (speedup 1.0000x reference)
#include <cuda_runtime.h>
#include <cuda_fp16.h>
#include <cstdint>

// B=8, C=512, NH=8, DH=64, N=H*W=1024
#define NB   8
#define NC   512
#define NH_  8
#define DH_  64
#define NSP  1024
#define NBH  64

// ---------------- static scratch (no allocation) -----------------------------
__device__ __half g_Wqkv_h[1536 * 512];
__device__ __half g_Wproj_h[512 * 512];
__device__ __half g_Watt1_h[128 * 512];
__device__ __half g_xch[NB * NC * NSP];       // [b][c][n] fp16 (layout-preserving)
__device__ __half g_qh[NBH * NSP * 64];       // [bh][n][d], pre-scaled by 0.125*log2e
__device__ __half g_kh[NBH * NSP * 64];       // [bh][n][d]
__device__ __half g_vth[NBH * DH_ * 1024];    // [bh][d][n] (V transposed)
__device__ __half g_oh[NB * NSP * 512];       // [b][sp][c] proj input (scramble-corrected)
__device__ __half g_outTh[NB * NSP * 512];    // [b][sp][o] proj out (att1 input)

// ---------------- helpers ----------------------------------------------------
__device__ __forceinline__ void cpa16(void* s, const void* g) {
    uint32_t sa = (uint32_t)__cvta_generic_to_shared(s);
    asm volatile("cp.async.cg.shared.global [%0], [%1], 16;\n" :: "r"(sa), "l"(g) : "memory");
}
__device__ __forceinline__ void cp_commit() {
    asm volatile("cp.async.commit_group;\n" ::: "memory");
}
template<int N> __device__ __forceinline__ void cp_wait() {
    asm volatile("cp.async.wait_group %0;\n" :: "n"(N) : "memory");
}
__device__ __forceinline__ void mma16816(float c[4], const uint32_t a[4], const uint32_t b[2]) {
    asm volatile(
        "mma.sync.aligned.m16n8k16.row.col.f32.f16.f16.f32 "
        "{%0,%1,%2,%3}, {%4,%5,%6,%7}, {%8,%9}, {%0,%1,%2,%3};\n"
        : "+f"(c[0]), "+f"(c[1]), "+f"(c[2]), "+f"(c[3])
        : "r"(a[0]), "r"(a[1]), "r"(a[2]), "r"(a[3]), "r"(b[0]), "r"(b[1]));
}
__device__ __forceinline__ void ldsm4(uint32_t r[4], const void* p) {
    uint32_t sa = (uint32_t)__cvta_generic_to_shared(p);
    asm volatile("ldmatrix.sync.aligned.m8n8.x4.shared.b16 {%0,%1,%2,%3}, [%4];"
        : "=r"(r[0]), "=r"(r[1]), "=r"(r[2]), "=r"(r[3]) : "r"(sa));
}
__device__ __forceinline__ void ldsm4t(uint32_t r[4], const void* p) {
    uint32_t sa = (uint32_t)__cvta_generic_to_shared(p);
    asm volatile("ldmatrix.sync.aligned.m8n8.x4.trans.shared.b16 {%0,%1,%2,%3}, [%4];"
        : "=r"(r[0]), "=r"(r[1]), "=r"(r[2]), "=r"(r[3]) : "r"(sa));
}
__device__ __forceinline__ uint32_t cvth2(float a, float b) {
    __half2 h = __floats2half2_rn(a, b);
    return *(uint32_t*)&h;
}
__device__ __forceinline__ uint32_t ex2h2(uint32_t x) {
    uint32_t r;
    asm("ex2.approx.f16x2 %0, %1;" : "=r"(r) : "r"(x));
    return r;
}

// ---------------- 128x64 fp16 GEMM core ([n][k] B), 256 threads --------------
#define BK   32
#define BSTR 40

__device__ __forceinline__ void gemm_core(
    const __half* __restrict__ A, const __half* __restrict__ B,
    int K, int m0, int n0, float acc[2][4][4])
{
    __shared__ __half As[3][128][BSTR];
    __shared__ __half Bs[3][64][BSTR];
    const int tid = threadIdx.x;
    const int lane = tid & 31;
    const int warp = tid >> 5;
    const int wm = warp >> 1, wn = warp & 1;
    const int KT = K / BK;
    const int arow = tid >> 1, alv = (tid & 1) * 2;
    const int brow = tid >> 2, bq = tid & 3;
    const int la = lane & 15, ha = (lane >> 4) * 8;
    const int lbr = (lane & 7) + ((lane >> 4) & 1) * 8;
    const int lbc = ((lane >> 3) & 1) * 8;

    auto issue = [&](int kt, int buf) {
        int kbase = kt * BK;
        const __half* ga = A + (size_t)(m0 + arow) * K + kbase + alv * 8;
        cpa16(&As[buf][arow][alv * 8], ga);
        cpa16(&As[buf][arow][(alv + 1) * 8], ga + 8);
        const __half* gb = B + (size_t)(n0 + brow) * K + kbase + bq * 8;
        cpa16(&Bs[buf][brow][bq * 8], gb);
        cp_commit();
    };

    auto compute = [&](int buf) {
        #pragma unroll
        for (int ks = 0; ks < 2; ks++) {
            int k0 = ks * 16;
            uint32_t af[2][4], bfr[4][2];
            #pragma unroll
            for (int mi = 0; mi < 2; mi++)
                ldsm4(af[mi], &As[buf][wm * 32 + mi * 16 + la][k0 + ha]);
            #pragma unroll
            for (int np = 0; np < 2; np++) {
                uint32_t bt[4];
                ldsm4(bt, &Bs[buf][wn * 32 + np * 16 + lbr][k0 + lbc]);
                bfr[2 * np][0] = bt[0]; bfr[2 * np][1] = bt[1];
                bfr[2 * np + 1][0] = bt[2]; bfr[2 * np + 1][1] = bt[3];
            }
            #pragma unroll
            for (int mi = 0; mi < 2; mi++)
                #pragma unroll
                for (int ni = 0; ni < 4; ni++)
                    mma16816(acc[mi][ni], af[mi], bfr[ni]);
        }
    };

    issue(0, 0);
    issue(1, 1);
    for (int kt = 0; kt < KT; kt++) {
        if (kt + 1 < KT) cp_wait<1>(); else cp_wait<0>();
        __syncthreads();
        if (kt + 2 < KT) issue(kt + 2, (kt + 2) % 3);
        compute(kt % 3);
    }
}

#define EPI_BEGIN                                                     \
    const int lane = threadIdx.x & 31;                                \
    const int warp = threadIdx.x >> 5;                                \
    const int wm = warp >> 1, wn = warp & 1;                          \
    _Pragma("unroll")                                                 \
    for (int mi = 0; mi < 2; mi++)                                    \
    _Pragma("unroll")                                                 \
    for (int ni = 0; ni < 4; ni++)                                    \
    _Pragma("unroll")                                                 \
    for (int e = 0; e < 4; e++) {                                     \
        int row = m0 + wm * 32 + mi * 16 + (lane >> 2) + ((e >> 1) * 8); \
        int col = n0 + wn * 32 + ni * 8 + 2 * (lane & 3) + (e & 1);   \
        float v = acc[mi][ni][e];
#define EPI_END }

// ---------------- prep kernels -----------------------------------------------
__global__ void k_prep_w_all(const float* __restrict__ Wqkv, const float* __restrict__ Wproj,
                             const float* __restrict__ Watt1,
                             __half* __restrict__ q_h, __half* __restrict__ p_h,
                             __half* __restrict__ a_h)
{
    int i = blockIdx.x * 256 + threadIdx.x;
    if (i < 786432)            q_h[i] = __float2half_rn(Wqkv[i]);
    else if (i < 1048576)      p_h[i - 786432] = __float2half_rn(Wproj[i - 786432]);
    else if (i < 1114112)      a_h[i - 1048576] = __float2half_rn(Watt1[i - 1048576]);
}

// layout-preserving fp32 -> fp16 stream convert of x
__global__ void k_prep_xc(const float* __restrict__ x)
{
    int i = blockIdx.x * 256 + threadIdx.x;
    float2 f2 = ((const float2*)x)[i];
    ((__half2*)g_xch)[i] = __floats2half2_rn(f2.x, f2.y);
}

// ---------------- qkv GEMM: B = x [c][n] via ldmatrix.trans ------------------
#define BSTR2 72

__global__ __launch_bounds__(256) void k_qkv_mma(void)
{
    __shared__ __half As[3][128][BSTR];
    __shared__ __half Bs[3][32][BSTR2];
    const int b = blockIdx.z;
    const int m0 = blockIdx.y * 128;   // o in [0,1536)
    const int n0 = blockIdx.x * 64;    // n
    const __half* A = g_Wqkv_h;
    const __half* X = g_xch + (size_t)b * NC * NSP;
    float acc[2][4][4] = {};

    const int tid = threadIdx.x;
    const int ln = tid & 31;
    const int wp = tid >> 5;
    const int wmq = wp >> 1, wnq = wp & 1;
    const int arow = tid >> 1, alv = (tid & 1) * 2;
    const int brow = tid >> 3, bch = tid & 7;
    const int laq = ln & 15, haq = (ln >> 4) * 8;
    const int tkr = (ln & 7) + ((ln >> 3) & 1) * 8;   // k row within 16
    const int tnc = ((ln >> 4) & 1) * 8;              // n col offset

    auto issue = [&](int kt, int buf) {
        int kbase = kt * BK;
        const __half* ga = A + (size_t)(m0 + arow) * 512 + kbase + alv * 8;
        cpa16(&As[buf][arow][alv * 8], ga);
        cpa16(&As[buf][arow][(alv + 1) * 8], ga + 8);
        // B: rows = c (32), cols = n (64 contiguous)
        const __half* gx = X + (size_t)(kbase + brow) * NSP + n0 + bch * 8;
        cpa16(&Bs[buf][brow][bch * 8], gx);
        cp_commit();
    };

    auto compute = [&](int buf) {
        #pragma unroll
        for (int ks = 0; ks < 2; ks++) {
            int k0 = ks * 16;
            uint32_t af[2][4], bfr[4][2];
            #pragma unroll
            for (int mi = 0; mi < 2; mi++)
                ldsm4(af[mi], &As[buf][wmq * 32 + mi * 16 + laq][k0 + haq]);
            #pragma unroll
            for (int np = 0; np < 2; np++) {
                uint32_t bt[4];
                ldsm4t(bt, &Bs[buf][k0 + tkr][wnq * 32 + np * 16 + tnc]);
                bfr[2 * np][0] = bt[0]; bfr[2 * np][1] = bt[1];
                bfr[2 * np + 1][0] = bt[2]; bfr[2 * np + 1][1] = bt[3];
            }
            #pragma unroll
            for (int mi = 0; mi < 2; mi++)
                #pragma unroll
                for (int ni = 0; ni < 4; ni++)
                    mma16816(acc[mi][ni], af[mi], bfr[ni]);
        }
    };

    issue(0, 0);
    issue(1, 1);
    for (int kt = 0; kt < 16; kt++) {
        if (kt + 1 < 16) cp_wait<1>(); else cp_wait<0>();
        __syncthreads();
        if (kt + 2 < 16) issue(kt + 2, (kt + 2) % 3);
        compute(kt % 3);
    }

    const float QSC = 0.125f * 1.4426950408889634f;   // fold log2e into q
    EPI_BEGIN
        int o = row, n = col;
        int t = o >> 9, h = (o >> 6) & 7, d = o & 63;
        int bh = b * 8 + h;
        if (t == 0)
            g_qh[((size_t)bh * NSP + n) * 64 + d] = __float2half_rn(v * QSC);
        else if (t == 1)
            g_kh[((size_t)bh * NSP + n) * 64 + d] = __float2half_rn(v);
        else
            g_vth[((size_t)bh * DH_ + d) * 1024 + n] = __float2half_rn(v);
    EPI_END
}

// ---------------- fused flash attention (64-row Q, 128 thr, 3 CTA/SM) --------
#define FSTR 72
#define FLASH_SMEM ((64 + 192 + 192) * FSTR * 2)

__global__ __launch_bounds__(128, 3) void k_flash(void)
{
    extern __shared__ __half fs[];
    __half* Qs = fs;                       // [64][FSTR]
    __half* Ks = fs + 64 * FSTR;           // [3][64][FSTR]
    __half* Vs = Ks + 3 * 64 * FSTR;       // [3][64][FSTR], rows = d, cols = kv

    const int tid = threadIdx.x, lane = tid & 31, warp = tid >> 5;  // warp 0..3
    const int bh = blockIdx.y, q0 = blockIdx.x * 64;
    const int b = bh >> 3, h = bh & 7;
    const __half* gq = g_qh + (size_t)bh * NSP * 64;
    const __half* gk = g_kh + (size_t)bh * NSP * 64;
    const __half* gv = g_vth + (size_t)bh * DH_ * 1024;
    const int la = lane & 15, ha = (lane >> 4) * 8;
    const int lbr = (lane & 7) + ((lane >> 4) & 1) * 8;
    const int lbc = ((lane >> 3) & 1) * 8;
    const uint32_t ONE2 = 0x3C003C00u;

    // Q tile load: 64 rows x 128B, 2 threads/row
    {
        int row = tid >> 1, hf = tid & 1;
        const __half* src = gq + (size_t)(q0 + row) * 64 + hf * 32;
        __half* dst = Qs + row * FSTR + hf * 32;
        #pragma unroll
        for (int s = 0; s < 4; s++) cpa16(dst + s * 8, src + s * 8);
        cp_commit();
    }

    auto issueKV = [&](int t, int buf) {
        int kv0 = t * 64;
        int row = tid >> 1, qd = tid & 1;   // 2 threads/row, 64B each
        {
            __half* dst = Ks + (buf * 64 + row) * FSTR + qd * 32;
            const __half* src = gk + (size_t)(kv0 + row) * 64 + qd * 32;
            #pragma unroll
            for (int s = 0; s < 4; s++) cpa16(dst + s * 8, src + s * 8);
        }
        {
            __half* dst = Vs + (buf * 64 + row) * FSTR + qd * 32;
            const __half* src = gv + (size_t)row * 1024 + kv0 + qd * 32;
            #pragma unroll
            for (int s = 0; s < 4; s++) cpa16(dst + s * 8, src + s * 8);
        }
        cp_commit();
    };

    float oacc[8][4] = {};
    float lacc[4] = {};

    issueKV(0, 0);
    issueKV(1, 1);

    for (int t = 0; t < 16; t++) {
        if (t + 1 < 16) cp_wait<1>(); else cp_wait<0>();
        __syncthreads();
        if (t + 2 < 16) issueKV(t + 2, (t + 2) % 3);

        int buf = t % 3;
        const __half* Kb = Ks + buf * 64 * FSTR;
        const __half* Vb = Vs + buf * 64 * FSTR;

        // ---- S = Q K^T (scores pre-scaled by log2e via q) ----
        float sacc[8][4] = {};
        #pragma unroll
        for (int ks = 0; ks < 4; ks++) {
            int k0 = ks * 16;
            uint32_t af[4];
            ldsm4(af, &Qs[(warp * 16 + la) * FSTR + k0 + ha]);
            #pragma unroll
            for (int jp = 0; jp < 4; jp++) {
                uint32_t bt[4];
                ldsm4(bt, &Kb[(jp * 16 + lbr) * FSTR + k0 + lbc]);
                uint32_t b0[2] = { bt[0], bt[1] }, b1[2] = { bt[2], bt[3] };
                mma16816(sacc[2 * jp], af, b0);
                mma16816(sacc[2 * jp + 1], af, b1);
            }
        }

        // ---- p = 2^sacc in fp16x2 ----
        uint32_t ph[8][2];
        #pragma unroll
        for (int j = 0; j < 8; j++) {
            ph[j][0] = ex2h2(cvth2(sacc[j][0], sacc[j][1]));
            ph[j][1] = ex2h2(cvth2(sacc[j][2], sacc[j][3]));
        }

        // ---- O += P V, l += P . 1 ----
        #pragma unroll
        for (int ks = 0; ks < 4; ks++) {
            int k0 = ks * 16;
            uint32_t af[4] = { ph[2 * ks][0], ph[2 * ks][1], ph[2 * ks + 1][0], ph[2 * ks + 1][1] };
            uint32_t bones[2] = { ONE2, ONE2 };
            mma16816(lacc, af, bones);
            #pragma unroll
            for (int jp = 0; jp < 4; jp++) {
                uint32_t bt[4];
                ldsm4(bt, &Vb[(jp * 16 + lbr) * FSTR + k0 + lbc]);
                uint32_t b0[2] = { bt[0], bt[1] }, b1[2] = { bt[2], bt[3] };
                mma16816(oacc[2 * jp], af, b0);
                mma16816(oacc[2 * jp + 1], af, b1);
            }
        }
    }

    // ---- normalize + scramble-corrected store ----
    float inv0 = 1.f / lacc[0], inv1 = 1.f / lacc[2];
    #pragma unroll
    for (int j = 0; j < 8; j++)
        #pragma unroll
        for (int e = 0; e < 4; e++) {
            int n = q0 + warp * 16 + (lane >> 2) + (e >> 1) * 8;
            int d = j * 8 + 2 * (lane & 3) + (e & 1);
            float v = oacc[j][e] * ((e < 2) ? inv0 : inv1);
            int flat = n * 512 + h * 64 + d;
            int c = flat >> 10;
            int sp = flat & 1023;
            g_oh[((size_t)b * NSP + sp) * 512 + c] = __float2half_rn(v);
        }
}

// ---------------- proj GEMM --------------------------------------------------
__global__ __launch_bounds__(256) void k_proj_mma(const float* __restrict__ bp,
                                                  float* __restrict__ out)
{
    int b = blockIdx.z;
    int m0 = blockIdx.y * 128;   // o
    int n0 = blockIdx.x * 64;    // sp
    float acc[2][4][4] = {};
    gemm_core(g_Wproj_h, g_oh + (size_t)b * NSP * 512, 512, m0, n0, acc);
    EPI_BEGIN
        float rr = v + bp[row];
        out[(size_t)b * 524288 + (size_t)row * NSP + col] = rr;
        g_outTh[((size_t)b * NSP + col) * 512 + row] = __float2half_rn(rr);
    EPI_END
}

// ---------------- fused att1 + att2 ------------------------------------------
__global__ __launch_bounds__(256) void k_att12(const float* __restrict__ b1,
                                               const float* __restrict__ W2,
                                               const float* __restrict__ b2,
                                               float* __restrict__ out)
{
    __shared__ float s_red[64];
    int b = blockIdx.y;
    int m0 = 0;
    int n0 = blockIdx.x * 64;    // sp
    float acc[2][4][4] = {};
    gemm_core(g_Watt1_h, g_outTh + (size_t)b * NSP * 512, 512, m0, n0, acc);

    if (threadIdx.x < 64) s_red[threadIdx.x] = 0.f;
    __syncthreads();

    {
        const int ln = threadIdx.x & 31;
        const int wp = threadIdx.x >> 5;
        const int wma = wp >> 1, wna = wp & 1;
        #pragma unroll
        for (int ni = 0; ni < 4; ni++) {
            #pragma unroll
            for (int eh = 0; eh < 2; eh++) {
                float p = 0.f;
                #pragma unroll
                for (int mi = 0; mi < 2; mi++)
                    #pragma unroll
                    for (int ev = 0; ev < 2; ev++) {
                        int row = wma * 32 + mi * 16 + (ln >> 2) + ev * 8;
                        float hv = fmaxf(acc[mi][ni][ev * 2 + eh] + b1[row], 0.f);
                        p = fmaf(W2[row], hv, p);
                    }
                p += __shfl_xor_sync(0xffffffffu, p, 4);
                p += __shfl_xor_sync(0xffffffffu, p, 8);
                p += __shfl_xor_sync(0xffffffffu, p, 16);
                if ((ln >> 2) == 0) {
                    int cl = wna * 32 + ni * 8 + 2 * (ln & 3) + eh;
                    atomicAdd(&s_red[cl], p);
                }
            }
        }
    }
    __syncthreads();
    if (threadIdx.x < 64) {
        float a = s_red[threadIdx.x] + b2[0];
        out[4194304 + b * NSP + n0 + threadIdx.x] = 1.f / (1.f + __expf(-a));
    }
}

// ---------------- final scale -------------------------------------------------
__global__ void k_scale(float* __restrict__ out)
{
    int idx = blockIdx.x * 256 + threadIdx.x;
    const float* sa = out + 4194304;
    int b  = idx >> 19;
    int sp = idx & 1023;
    out[idx] *= sa[b * NSP + sp];
}

// ---------------- launch ------------------------------------------------------
extern "C" void kernel_launch(void* const* d_in, const int* in_sizes, int n_in,
                              void* d_out, int out_size)
{
    const float* x     = (const float*)d_in[0];
    const float* Wqkv  = (const float*)d_in[1];
    const float* Wproj = (const float*)d_in[2];
    const float* bproj = (const float*)d_in[3];
    const float* Watt1 = (const float*)d_in[4];
    const float* batt1 = (const float*)d_in[5];
    const float* Watt2 = (const float*)d_in[6];
    const float* batt2 = (const float*)d_in[7];
    float* out = (float*)d_out;

    __half *wqkv_h, *wproj_h, *watt1_h;
    cudaGetSymbolAddress((void**)&wqkv_h,  g_Wqkv_h);
    cudaGetSymbolAddress((void**)&wproj_h, g_Wproj_h);
    cudaGetSymbolAddress((void**)&watt1_h, g_Watt1_h);

    cudaFuncSetAttribute(k_flash, cudaFuncAttributeMaxDynamicSharedMemorySize, FLASH_SMEM);

    k_prep_w_all<<<4352, 256>>>(Wqkv, Wproj, Watt1, wqkv_h, wproj_h, watt1_h);
    k_prep_xc<<<8192, 256>>>(x);

    k_qkv_mma <<<dim3(16, 12, 8), 256>>>();
    k_flash   <<<dim3(16, 64), 128, FLASH_SMEM>>>();
    k_proj_mma<<<dim3(16, 4, 8),  256>>>(bproj, out);
    k_att12   <<<dim3(16, 8),     256>>>(batt1, Watt2, batt2, out);
    k_scale   <<<16384, 256>>>(out);
}

// round 13
// speedup vs baseline: 1.0680x; 1.0680x over previous
#include <cuda_runtime.h>
#include <cuda_fp16.h>
#include <cstdint>

// B=8, C=512, NH=8, DH=64, N=H*W=1024
#define NB   8
#define NC   512
#define NH_  8
#define DH_  64
#define NSP  1024
#define NBH  64

// ---------------- static scratch (no allocation) -----------------------------
__device__ __half g_Wqkv_h[1536 * 512];
__device__ __half g_Wproj_h[512 * 512];
__device__ __half g_Watt1_h[128 * 512];
__device__ __half g_xch[NB * NC * NSP];       // [b][c][n] fp16 (layout-preserving)
__device__ __half g_qh[NBH * NSP * 64];       // [bh][n][d], pre-scaled by 0.125*log2e
__device__ __half g_kh[NBH * NSP * 64];       // [bh][n][d]
__device__ __half g_vth[NBH * DH_ * 1024];    // [bh][d][n] (V transposed)
__device__ __half g_oh[NB * NSP * 512];       // [b][sp][c] proj input (scramble-corrected)
__device__ __half g_outTh[NB * NSP * 512];    // [b][sp][o] proj out (att1 input)

// ---------------- helpers ----------------------------------------------------
__device__ __forceinline__ void cpa16(void* s, const void* g) {
    uint32_t sa = (uint32_t)__cvta_generic_to_shared(s);
    asm volatile("cp.async.cg.shared.global [%0], [%1], 16;\n" :: "r"(sa), "l"(g) : "memory");
}
__device__ __forceinline__ void cp_commit() {
    asm volatile("cp.async.commit_group;\n" ::: "memory");
}
template<int N> __device__ __forceinline__ void cp_wait() {
    asm volatile("cp.async.wait_group %0;\n" :: "n"(N) : "memory");
}
__device__ __forceinline__ void mma16816(float c[4], const uint32_t a[4], const uint32_t b[2]) {
    asm volatile(
        "mma.sync.aligned.m16n8k16.row.col.f32.f16.f16.f32 "
        "{%0,%1,%2,%3}, {%4,%5,%6,%7}, {%8,%9}, {%0,%1,%2,%3};\n"
        : "+f"(c[0]), "+f"(c[1]), "+f"(c[2]), "+f"(c[3])
        : "r"(a[0]), "r"(a[1]), "r"(a[2]), "r"(a[3]), "r"(b[0]), "r"(b[1]));
}
__device__ __forceinline__ void ldsm4(uint32_t r[4], const void* p) {
    uint32_t sa = (uint32_t)__cvta_generic_to_shared(p);
    asm volatile("ldmatrix.sync.aligned.m8n8.x4.shared.b16 {%0,%1,%2,%3}, [%4];"
        : "=r"(r[0]), "=r"(r[1]), "=r"(r[2]), "=r"(r[3]) : "r"(sa));
}
__device__ __forceinline__ void ldsm4t(uint32_t r[4], const void* p) {
    uint32_t sa = (uint32_t)__cvta_generic_to_shared(p);
    asm volatile("ldmatrix.sync.aligned.m8n8.x4.trans.shared.b16 {%0,%1,%2,%3}, [%4];"
        : "=r"(r[0]), "=r"(r[1]), "=r"(r[2]), "=r"(r[3]) : "r"(sa));
}
__device__ __forceinline__ uint32_t cvth2(float a, float b) {
    __half2 h = __floats2half2_rn(a, b);
    return *(uint32_t*)&h;
}
__device__ __forceinline__ uint32_t ex2h2(uint32_t x) {
    uint32_t r;
    asm("ex2.approx.f16x2 %0, %1;" : "=r"(r) : "r"(x));
    return r;
}

// ---------------- 128x64 fp16 GEMM core ([n][k] B), 256 threads --------------
#define BK   32
#define BSTR 40

__device__ __forceinline__ void gemm_core(
    const __half* __restrict__ A, const __half* __restrict__ B,
    int K, int m0, int n0, float acc[2][4][4])
{
    __shared__ __half As[3][128][BSTR];
    __shared__ __half Bs[3][64][BSTR];
    const int tid = threadIdx.x;
    const int lane = tid & 31;
    const int warp = tid >> 5;
    const int wm = warp >> 1, wn = warp & 1;
    const int KT = K / BK;
    const int arow = tid >> 1, alv = (tid & 1) * 2;
    const int brow = tid >> 2, bq = tid & 3;
    const int la = lane & 15, ha = (lane >> 4) * 8;
    const int lbr = (lane & 7) + ((lane >> 4) & 1) * 8;
    const int lbc = ((lane >> 3) & 1) * 8;

    auto issue = [&](int kt, int buf) {
        int kbase = kt * BK;
        const __half* ga = A + (size_t)(m0 + arow) * K + kbase + alv * 8;
        cpa16(&As[buf][arow][alv * 8], ga);
        cpa16(&As[buf][arow][(alv + 1) * 8], ga + 8);
        const __half* gb = B + (size_t)(n0 + brow) * K + kbase + bq * 8;
        cpa16(&Bs[buf][brow][bq * 8], gb);
        cp_commit();
    };

    auto compute = [&](int buf) {
        #pragma unroll
        for (int ks = 0; ks < 2; ks++) {
            int k0 = ks * 16;
            uint32_t af[2][4], bfr[4][2];
            #pragma unroll
            for (int mi = 0; mi < 2; mi++)
                ldsm4(af[mi], &As[buf][wm * 32 + mi * 16 + la][k0 + ha]);
            #pragma unroll
            for (int np = 0; np < 2; np++) {
                uint32_t bt[4];
                ldsm4(bt, &Bs[buf][wn * 32 + np * 16 + lbr][k0 + lbc]);
                bfr[2 * np][0] = bt[0]; bfr[2 * np][1] = bt[1];
                bfr[2 * np + 1][0] = bt[2]; bfr[2 * np + 1][1] = bt[3];
            }
            #pragma unroll
            for (int mi = 0; mi < 2; mi++)
                #pragma unroll
                for (int ni = 0; ni < 4; ni++)
                    mma16816(acc[mi][ni], af[mi], bfr[ni]);
        }
    };

    issue(0, 0);
    issue(1, 1);
    for (int kt = 0; kt < KT; kt++) {
        if (kt + 1 < KT) cp_wait<1>(); else cp_wait<0>();
        __syncthreads();
        if (kt + 2 < KT) issue(kt + 2, (kt + 2) % 3);
        compute(kt % 3);
    }
}

#define EPI_BEGIN                                                     \
    const int lane = threadIdx.x & 31;                                \
    const int warp = threadIdx.x >> 5;                                \
    const int wm = warp >> 1, wn = warp & 1;                          \
    _Pragma("unroll")                                                 \
    for (int mi = 0; mi < 2; mi++)                                    \
    _Pragma("unroll")                                                 \
    for (int ni = 0; ni < 4; ni++)                                    \
    _Pragma("unroll")                                                 \
    for (int e = 0; e < 4; e++) {                                     \
        int row = m0 + wm * 32 + mi * 16 + (lane >> 2) + ((e >> 1) * 8); \
        int col = n0 + wn * 32 + ni * 8 + 2 * (lane & 3) + (e & 1);   \
        float v = acc[mi][ni][e];
#define EPI_END }

// ---------------- prep kernels -----------------------------------------------
__global__ void k_prep_w_all(const float* __restrict__ Wqkv, const float* __restrict__ Wproj,
                             const float* __restrict__ Watt1,
                             __half* __restrict__ q_h, __half* __restrict__ p_h,
                             __half* __restrict__ a_h)
{
    int i = blockIdx.x * 256 + threadIdx.x;
    if (i < 786432)            q_h[i] = __float2half_rn(Wqkv[i]);
    else if (i < 1048576)      p_h[i - 786432] = __float2half_rn(Wproj[i - 786432]);
    else if (i < 1114112)      a_h[i - 1048576] = __float2half_rn(Watt1[i - 1048576]);
}

// layout-preserving fp32 -> fp16 stream convert of x
__global__ void k_prep_xc(const float* __restrict__ x)
{
    int i = blockIdx.x * 256 + threadIdx.x;
    float2 f2 = ((const float2*)x)[i];
    ((__half2*)g_xch)[i] = __floats2half2_rn(f2.x, f2.y);
}

// ---------------- qkv GEMM: B = x [c][n] via ldmatrix.trans ------------------
#define BSTR2 72

__global__ __launch_bounds__(256) void k_qkv_mma(void)
{
    __shared__ __half As[3][128][BSTR];
    __shared__ __half Bs[3][32][BSTR2];
    const int b = blockIdx.z;
    const int m0 = blockIdx.y * 128;   // o in [0,1536)
    const int n0 = blockIdx.x * 64;    // n
    const __half* A = g_Wqkv_h;
    const __half* X = g_xch + (size_t)b * NC * NSP;
    float acc[2][4][4] = {};

    const int tid = threadIdx.x;
    const int ln = tid & 31;
    const int wp = tid >> 5;
    const int wmq = wp >> 1, wnq = wp & 1;
    const int arow = tid >> 1, alv = (tid & 1) * 2;
    const int brow = tid >> 3, bch = tid & 7;
    const int laq = ln & 15, haq = (ln >> 4) * 8;
    const int tkr = (ln & 7) + ((ln >> 3) & 1) * 8;   // k row within 16
    const int tnc = ((ln >> 4) & 1) * 8;              // n col offset

    auto issue = [&](int kt, int buf) {
        int kbase = kt * BK;
        const __half* ga = A + (size_t)(m0 + arow) * 512 + kbase + alv * 8;
        cpa16(&As[buf][arow][alv * 8], ga);
        cpa16(&As[buf][arow][(alv + 1) * 8], ga + 8);
        const __half* gx = X + (size_t)(kbase + brow) * NSP + n0 + bch * 8;
        cpa16(&Bs[buf][brow][bch * 8], gx);
        cp_commit();
    };

    auto compute = [&](int buf) {
        #pragma unroll
        for (int ks = 0; ks < 2; ks++) {
            int k0 = ks * 16;
            uint32_t af[2][4], bfr[4][2];
            #pragma unroll
            for (int mi = 0; mi < 2; mi++)
                ldsm4(af[mi], &As[buf][wmq * 32 + mi * 16 + laq][k0 + haq]);
            #pragma unroll
            for (int np = 0; np < 2; np++) {
                uint32_t bt[4];
                ldsm4t(bt, &Bs[buf][k0 + tkr][wnq * 32 + np * 16 + tnc]);
                bfr[2 * np][0] = bt[0]; bfr[2 * np][1] = bt[1];
                bfr[2 * np + 1][0] = bt[2]; bfr[2 * np + 1][1] = bt[3];
            }
            #pragma unroll
            for (int mi = 0; mi < 2; mi++)
                #pragma unroll
                for (int ni = 0; ni < 4; ni++)
                    mma16816(acc[mi][ni], af[mi], bfr[ni]);
        }
    };

    issue(0, 0);
    issue(1, 1);
    for (int kt = 0; kt < 16; kt++) {
        if (kt + 1 < 16) cp_wait<1>(); else cp_wait<0>();
        __syncthreads();
        if (kt + 2 < 16) issue(kt + 2, (kt + 2) % 3);
        compute(kt % 3);
    }

    const float QSC = 0.125f * 1.4426950408889634f;   // fold log2e into q
    EPI_BEGIN
        int o = row, n = col;
        int t = o >> 9, h = (o >> 6) & 7, d = o & 63;
        int bh = b * 8 + h;
        if (t == 0)
            g_qh[((size_t)bh * NSP + n) * 64 + d] = __float2half_rn(v * QSC);
        else if (t == 1)
            g_kh[((size_t)bh * NSP + n) * 64 + d] = __float2half_rn(v);
        else
            g_vth[((size_t)bh * DH_ + d) * 1024 + n] = __float2half_rn(v);
    EPI_END
}

// ---------------- fused flash attention (128-row Q, 256 thr, 2 CTA/SM) -------
#define FSTR 72
#define FLASH_SMEM ((128 + 192 + 192) * FSTR * 2)

__global__ __launch_bounds__(256, 2) void k_flash(void)
{
    extern __shared__ __half fs[];
    __half* Qs = fs;                       // [128][FSTR]
    __half* Ks = fs + 128 * FSTR;          // [3][64][FSTR]
    __half* Vs = Ks + 3 * 64 * FSTR;       // [3][64][FSTR], rows = d, cols = kv

    const int tid = threadIdx.x, lane = tid & 31, warp = tid >> 5;
    const int bh = blockIdx.y, q0 = blockIdx.x * 128;
    const int b = bh >> 3, h = bh & 7;
    const __half* gq = g_qh + (size_t)bh * NSP * 64;
    const __half* gk = g_kh + (size_t)bh * NSP * 64;
    const __half* gv = g_vth + (size_t)bh * DH_ * 1024;
    const int la = lane & 15, ha = (lane >> 4) * 8;
    const int lbr = (lane & 7) + ((lane >> 4) & 1) * 8;
    const int lbc = ((lane >> 3) & 1) * 8;
    const uint32_t ONE2 = 0x3C003C00u;

    {
        int row = tid >> 1, hf = tid & 1;
        const __half* src = gq + (size_t)(q0 + row) * 64 + hf * 32;
        __half* dst = Qs + row * FSTR + hf * 32;
        #pragma unroll
        for (int s = 0; s < 4; s++) cpa16(dst + s * 8, src + s * 8);
        cp_commit();
    }

    auto issueKV = [&](int t, int buf) {
        int kv0 = t * 64;
        int row = tid >> 2, qd = tid & 3;
        {
            __half* dst = Ks + (buf * 64 + row) * FSTR;
            const __half* src = gk + (size_t)(kv0 + row) * 64;
            cpa16(dst + qd * 16,     src + qd * 16);
            cpa16(dst + qd * 16 + 8, src + qd * 16 + 8);
        }
        {
            __half* dst = Vs + (buf * 64 + row) * FSTR;      // row = d
            const __half* src = gv + (size_t)row * 1024 + kv0;
            cpa16(dst + qd * 16,     src + qd * 16);
            cpa16(dst + qd * 16 + 8, src + qd * 16 + 8);
        }
        cp_commit();
    };

    float oacc[8][4] = {};
    float lacc[4] = {};

    issueKV(0, 0);
    issueKV(1, 1);

    for (int t = 0; t < 16; t++) {
        if (t + 1 < 16) cp_wait<1>(); else cp_wait<0>();
        __syncthreads();
        if (t + 2 < 16) issueKV(t + 2, (t + 2) % 3);

        int buf = t % 3;
        const __half* Kb = Ks + buf * 64 * FSTR;
        const __half* Vb = Vs + buf * 64 * FSTR;

        // ---- S = Q K^T (scores pre-scaled by log2e via q) ----
        float sacc[8][4] = {};
        #pragma unroll
        for (int ks = 0; ks < 4; ks++) {
            int k0 = ks * 16;
            uint32_t af[4];
            ldsm4(af, &Qs[(warp * 16 + la) * FSTR + k0 + ha]);
            #pragma unroll
            for (int jp = 0; jp < 4; jp++) {
                uint32_t bt[4];
                ldsm4(bt, &Kb[(jp * 16 + lbr) * FSTR + k0 + lbc]);
                uint32_t b0[2] = { bt[0], bt[1] }, b1[2] = { bt[2], bt[3] };
                mma16816(sacc[2 * jp], af, b0);
                mma16816(sacc[2 * jp + 1], af, b1);
            }
        }

        // ---- p = 2^sacc in fp16x2 ----
        uint32_t ph[8][2];
        #pragma unroll
        for (int j = 0; j < 8; j++) {
            ph[j][0] = ex2h2(cvth2(sacc[j][0], sacc[j][1]));
            ph[j][1] = ex2h2(cvth2(sacc[j][2], sacc[j][3]));
        }

        // ---- O += P V, l += P . 1 ----
        #pragma unroll
        for (int ks = 0; ks < 4; ks++) {
            int k0 = ks * 16;
            uint32_t af[4] = { ph[2 * ks][0], ph[2 * ks][1], ph[2 * ks + 1][0], ph[2 * ks + 1][1] };
            uint32_t bones[2] = { ONE2, ONE2 };
            mma16816(lacc, af, bones);
            #pragma unroll
            for (int jp = 0; jp < 4; jp++) {
                uint32_t bt[4];
                ldsm4(bt, &Vb[(jp * 16 + lbr) * FSTR + k0 + lbc]);
                uint32_t b0[2] = { bt[0], bt[1] }, b1[2] = { bt[2], bt[3] };
                mma16816(oacc[2 * jp], af, b0);
                mma16816(oacc[2 * jp + 1], af, b1);
            }
        }
    }

    // ---- normalize + scramble-corrected store ----
    float inv0 = 1.f / lacc[0], inv1 = 1.f / lacc[2];
    #pragma unroll
    for (int j = 0; j < 8; j++)
        #pragma unroll
        for (int e = 0; e < 4; e++) {
            int n = q0 + warp * 16 + (lane >> 2) + (e >> 1) * 8;
            int d = j * 8 + 2 * (lane & 3) + (e & 1);
            float v = oacc[j][e] * ((e < 2) ? inv0 : inv1);
            int flat = n * 512 + h * 64 + d;
            int c = flat >> 10;
            int sp = flat & 1023;
            g_oh[((size_t)b * NSP + sp) * 512 + c] = __float2half_rn(v);
        }
}

// ---------------- proj GEMM --------------------------------------------------
__global__ __launch_bounds__(256) void k_proj_mma(const float* __restrict__ bp,
                                                  float* __restrict__ out)
{
    int b = blockIdx.z;
    int m0 = blockIdx.y * 128;   // o
    int n0 = blockIdx.x * 64;    // sp
    float acc[2][4][4] = {};
    gemm_core(g_Wproj_h, g_oh + (size_t)b * NSP * 512, 512, m0, n0, acc);
    EPI_BEGIN
        float rr = v + bp[row];
        out[(size_t)b * 524288 + (size_t)row * NSP + col] = rr;
        g_outTh[((size_t)b * NSP + col) * 512 + row] = __float2half_rn(rr);
    EPI_END
}

// ---------------- fused att1 + att2 ------------------------------------------
__global__ __launch_bounds__(256) void k_att12(const float* __restrict__ b1,
                                               const float* __restrict__ W2,
                                               const float* __restrict__ b2,
                                               float* __restrict__ out)
{
    __shared__ float s_red[64];
    int b = blockIdx.y;
    int m0 = 0;
    int n0 = blockIdx.x * 64;    // sp
    float acc[2][4][4] = {};
    gemm_core(g_Watt1_h, g_outTh + (size_t)b * NSP * 512, 512, m0, n0, acc);

    if (threadIdx.x < 64) s_red[threadIdx.x] = 0.f;
    __syncthreads();

    {
        const int ln = threadIdx.x & 31;
        const int wp = threadIdx.x >> 5;
        const int wma = wp >> 1, wna = wp & 1;
        #pragma unroll
        for (int ni = 0; ni < 4; ni++) {
            #pragma unroll
            for (int eh = 0; eh < 2; eh++) {
                float p = 0.f;
                #pragma unroll
                for (int mi = 0; mi < 2; mi++)
                    #pragma unroll
                    for (int ev = 0; ev < 2; ev++) {
                        int row = wma * 32 + mi * 16 + (ln >> 2) + ev * 8;
                        float hv = fmaxf(acc[mi][ni][ev * 2 + eh] + b1[row], 0.f);
                        p = fmaf(W2[row], hv, p);
                    }
                p += __shfl_xor_sync(0xffffffffu, p, 4);
                p += __shfl_xor_sync(0xffffffffu, p, 8);
                p += __shfl_xor_sync(0xffffffffu, p, 16);
                if ((ln >> 2) == 0) {
                    int cl = wna * 32 + ni * 8 + 2 * (ln & 3) + eh;
                    atomicAdd(&s_red[cl], p);
                }
            }
        }
    }
    __syncthreads();
    if (threadIdx.x < 64) {
        float a = s_red[threadIdx.x] + b2[0];
        out[4194304 + b * NSP + n0 + threadIdx.x] = 1.f / (1.f + __expf(-a));
    }
}

// ---------------- final scale -------------------------------------------------
__global__ void k_scale(float* __restrict__ out)
{
    int idx = blockIdx.x * 256 + threadIdx.x;
    const float* sa = out + 4194304;
    int b  = idx >> 19;
    int sp = idx & 1023;
    out[idx] *= sa[b * NSP + sp];
}

// ---------------- launch ------------------------------------------------------
extern "C" void kernel_launch(void* const* d_in, const int* in_sizes, int n_in,
                              void* d_out, int out_size)
{
    const float* x     = (const float*)d_in[0];
    const float* Wqkv  = (const float*)d_in[1];
    const float* Wproj = (const float*)d_in[2];
    const float* bproj = (const float*)d_in[3];
    const float* Watt1 = (const float*)d_in[4];
    const float* batt1 = (const float*)d_in[5];
    const float* Watt2 = (const float*)d_in[6];
    const float* batt2 = (const float*)d_in[7];
    float* out = (float*)d_out;

    __half *wqkv_h, *wproj_h, *watt1_h;
    cudaGetSymbolAddress((void**)&wqkv_h,  g_Wqkv_h);
    cudaGetSymbolAddress((void**)&wproj_h, g_Wproj_h);
    cudaGetSymbolAddress((void**)&watt1_h, g_Watt1_h);

    cudaFuncSetAttribute(k_flash, cudaFuncAttributeMaxDynamicSharedMemorySize, FLASH_SMEM);

    k_prep_w_all<<<4352, 256>>>(Wqkv, Wproj, Watt1, wqkv_h, wproj_h, watt1_h);
    k_prep_xc<<<8192, 256>>>(x);

    k_qkv_mma <<<dim3(16, 12, 8), 256>>>();
    k_flash   <<<dim3(8, 64), 256, FLASH_SMEM>>>();
    k_proj_mma<<<dim3(16, 4, 8),  256>>>(bproj, out);
    k_att12   <<<dim3(16, 8),     256>>>(batt1, Watt2, batt2, out);
    k_scale   <<<16384, 256>>>(out);
}

// round 14
// speedup vs baseline: 1.0798x; 1.0110x over previous
#include <cuda_runtime.h>
#include <cuda_fp16.h>
#include <cstdint>

// B=8, C=512, NH=8, DH=64, N=H*W=1024
#define NB   8
#define NC   512
#define NH_  8
#define DH_  64
#define NSP  1024
#define NBH  64

// ---------------- static scratch (no allocation) -----------------------------
__device__ __half g_Wqkv_h[1536 * 512];
__device__ __half g_Wproj_h[512 * 512];
__device__ __half g_Watt1_h[128 * 512];
__device__ __half g_xch[NB * NC * NSP];       // [b][c][n] fp16 (layout-preserving)
__device__ __half g_qh[NBH * NSP * 64];       // [bh][n][d], pre-scaled by 0.125*log2e
__device__ __half g_kh[NBH * NSP * 64];       // [bh][n][d]
__device__ __half g_vth[NBH * DH_ * 1024];    // [bh][d][n] (V transposed)
__device__ __half g_oh[NB * NSP * 512];       // [b][sp][c] proj input (scramble-corrected)
__device__ __half g_outh[NB * 512 * NSP];     // [b][o][sp] proj out fp16 (att1 input, c-major)

// ---------------- helpers ----------------------------------------------------
__device__ __forceinline__ void cpa16(void* s, const void* g) {
    uint32_t sa = (uint32_t)__cvta_generic_to_shared(s);
    asm volatile("cp.async.cg.shared.global [%0], [%1], 16;\n" :: "r"(sa), "l"(g) : "memory");
}
__device__ __forceinline__ void cp_commit() {
    asm volatile("cp.async.commit_group;\n" ::: "memory");
}
template<int N> __device__ __forceinline__ void cp_wait() {
    asm volatile("cp.async.wait_group %0;\n" :: "n"(N) : "memory");
}
__device__ __forceinline__ void mma16816(float c[4], const uint32_t a[4], const uint32_t b[2]) {
    asm volatile(
        "mma.sync.aligned.m16n8k16.row.col.f32.f16.f16.f32 "
        "{%0,%1,%2,%3}, {%4,%5,%6,%7}, {%8,%9}, {%0,%1,%2,%3};\n"
        : "+f"(c[0]), "+f"(c[1]), "+f"(c[2]), "+f"(c[3])
        : "r"(a[0]), "r"(a[1]), "r"(a[2]), "r"(a[3]), "r"(b[0]), "r"(b[1]));
}
__device__ __forceinline__ void ldsm4(uint32_t r[4], const void* p) {
    uint32_t sa = (uint32_t)__cvta_generic_to_shared(p);
    asm volatile("ldmatrix.sync.aligned.m8n8.x4.shared.b16 {%0,%1,%2,%3}, [%4];"
        : "=r"(r[0]), "=r"(r[1]), "=r"(r[2]), "=r"(r[3]) : "r"(sa));
}
__device__ __forceinline__ void ldsm4t(uint32_t r[4], const void* p) {
    uint32_t sa = (uint32_t)__cvta_generic_to_shared(p);
    asm volatile("ldmatrix.sync.aligned.m8n8.x4.trans.shared.b16 {%0,%1,%2,%3}, [%4];"
        : "=r"(r[0]), "=r"(r[1]), "=r"(r[2]), "=r"(r[3]) : "r"(sa));
}
__device__ __forceinline__ uint32_t cvth2(float a, float b) {
    __half2 h = __floats2half2_rn(a, b);
    return *(uint32_t*)&h;
}
__device__ __forceinline__ uint32_t ex2h2(uint32_t x) {
    uint32_t r;
    asm("ex2.approx.f16x2 %0, %1;" : "=r"(r) : "r"(x));
    return r;
}

// ---------------- 128x64 fp16 GEMM core ([n][k] B), 256 threads --------------
#define BK   32
#define BSTR 40

__device__ __forceinline__ void gemm_core(
    const __half* __restrict__ A, const __half* __restrict__ B,
    int K, int m0, int n0, float acc[2][4][4])
{
    __shared__ __half As[3][128][BSTR];
    __shared__ __half Bs[3][64][BSTR];
    const int tid = threadIdx.x;
    const int lane = tid & 31;
    const int warp = tid >> 5;
    const int wm = warp >> 1, wn = warp & 1;
    const int KT = K / BK;
    const int arow = tid >> 1, alv = (tid & 1) * 2;
    const int brow = tid >> 2, bq = tid & 3;
    const int la = lane & 15, ha = (lane >> 4) * 8;
    const int lbr = (lane & 7) + ((lane >> 4) & 1) * 8;
    const int lbc = ((lane >> 3) & 1) * 8;

    auto issue = [&](int kt, int buf) {
        int kbase = kt * BK;
        const __half* ga = A + (size_t)(m0 + arow) * K + kbase + alv * 8;
        cpa16(&As[buf][arow][alv * 8], ga);
        cpa16(&As[buf][arow][(alv + 1) * 8], ga + 8);
        const __half* gb = B + (size_t)(n0 + brow) * K + kbase + bq * 8;
        cpa16(&Bs[buf][brow][bq * 8], gb);
        cp_commit();
    };

    auto compute = [&](int buf) {
        #pragma unroll
        for (int ks = 0; ks < 2; ks++) {
            int k0 = ks * 16;
            uint32_t af[2][4], bfr[4][2];
            #pragma unroll
            for (int mi = 0; mi < 2; mi++)
                ldsm4(af[mi], &As[buf][wm * 32 + mi * 16 + la][k0 + ha]);
            #pragma unroll
            for (int np = 0; np < 2; np++) {
                uint32_t bt[4];
                ldsm4(bt, &Bs[buf][wn * 32 + np * 16 + lbr][k0 + lbc]);
                bfr[2 * np][0] = bt[0]; bfr[2 * np][1] = bt[1];
                bfr[2 * np + 1][0] = bt[2]; bfr[2 * np + 1][1] = bt[3];
            }
            #pragma unroll
            for (int mi = 0; mi < 2; mi++)
                #pragma unroll
                for (int ni = 0; ni < 4; ni++)
                    mma16816(acc[mi][ni], af[mi], bfr[ni]);
        }
    };

    issue(0, 0);
    issue(1, 1);
    for (int kt = 0; kt < KT; kt++) {
        if (kt + 1 < KT) cp_wait<1>(); else cp_wait<0>();
        __syncthreads();
        if (kt + 2 < KT) issue(kt + 2, (kt + 2) % 3);
        compute(kt % 3);
    }
}

#define EPI_BEGIN                                                     \
    const int lane = threadIdx.x & 31;                                \
    const int warp = threadIdx.x >> 5;                                \
    const int wm = warp >> 1, wn = warp & 1;                          \
    _Pragma("unroll")                                                 \
    for (int mi = 0; mi < 2; mi++)                                    \
    _Pragma("unroll")                                                 \
    for (int ni = 0; ni < 4; ni++)                                    \
    _Pragma("unroll")                                                 \
    for (int e = 0; e < 4; e++) {                                     \
        int row = m0 + wm * 32 + mi * 16 + (lane >> 2) + ((e >> 1) * 8); \
        int col = n0 + wn * 32 + ni * 8 + 2 * (lane & 3) + (e & 1);   \
        float v = acc[mi][ni][e];
#define EPI_END }

// ---------------- prep kernels -----------------------------------------------
__global__ void k_prep_w_all(const float* __restrict__ Wqkv, const float* __restrict__ Wproj,
                             const float* __restrict__ Watt1,
                             __half* __restrict__ q_h, __half* __restrict__ p_h,
                             __half* __restrict__ a_h)
{
    int i = blockIdx.x * 256 + threadIdx.x;
    if (i < 786432)            q_h[i] = __float2half_rn(Wqkv[i]);
    else if (i < 1048576)      p_h[i - 786432] = __float2half_rn(Wproj[i - 786432]);
    else if (i < 1114112)      a_h[i - 1048576] = __float2half_rn(Watt1[i - 1048576]);
}

// layout-preserving fp32 -> fp16 stream convert of x
__global__ void k_prep_xc(const float* __restrict__ x)
{
    int i = blockIdx.x * 256 + threadIdx.x;
    float2 f2 = ((const float2*)x)[i];
    ((__half2*)g_xch)[i] = __floats2half2_rn(f2.x, f2.y);
}

// ---------------- qkv GEMM: B = x [c][n] via ldmatrix.trans, staged epi ------
#define BSTR2 72

__global__ __launch_bounds__(256) void k_qkv_mma(void)
{
    __shared__ __half As[3][128][BSTR];
    __shared__ __half Bs[3][32][BSTR2];
    const int b = blockIdx.z;
    const int m0 = blockIdx.y * 128;   // o in [0,1536), block entirely q, k, or v
    const int n0 = blockIdx.x * 64;    // n
    const __half* A = g_Wqkv_h;
    const __half* X = g_xch + (size_t)b * NC * NSP;
    float acc[2][4][4] = {};

    const int tid = threadIdx.x;
    const int ln = tid & 31;
    const int wp = tid >> 5;
    const int wmq = wp >> 1, wnq = wp & 1;
    const int arow = tid >> 1, alv = (tid & 1) * 2;
    const int brow = tid >> 3, bch = tid & 7;
    const int laq = ln & 15, haq = (ln >> 4) * 8;
    const int tkr = (ln & 7) + ((ln >> 3) & 1) * 8;
    const int tnc = ((ln >> 4) & 1) * 8;

    auto issue = [&](int kt, int buf) {
        int kbase = kt * BK;
        const __half* ga = A + (size_t)(m0 + arow) * 512 + kbase + alv * 8;
        cpa16(&As[buf][arow][alv * 8], ga);
        cpa16(&As[buf][arow][(alv + 1) * 8], ga + 8);
        const __half* gx = X + (size_t)(kbase + brow) * NSP + n0 + bch * 8;
        cpa16(&Bs[buf][brow][bch * 8], gx);
        cp_commit();
    };

    auto compute = [&](int buf) {
        #pragma unroll
        for (int ks = 0; ks < 2; ks++) {
            int k0 = ks * 16;
            uint32_t af[2][4], bfr[4][2];
            #pragma unroll
            for (int mi = 0; mi < 2; mi++)
                ldsm4(af[mi], &As[buf][wmq * 32 + mi * 16 + laq][k0 + haq]);
            #pragma unroll
            for (int np = 0; np < 2; np++) {
                uint32_t bt[4];
                ldsm4t(bt, &Bs[buf][k0 + tkr][wnq * 32 + np * 16 + tnc]);
                bfr[2 * np][0] = bt[0]; bfr[2 * np][1] = bt[1];
                bfr[2 * np + 1][0] = bt[2]; bfr[2 * np + 1][1] = bt[3];
            }
            #pragma unroll
            for (int mi = 0; mi < 2; mi++)
                #pragma unroll
                for (int ni = 0; ni < 4; ni++)
                    mma16816(acc[mi][ni], af[mi], bfr[ni]);
        }
    };

    issue(0, 0);
    issue(1, 1);
    for (int kt = 0; kt < 16; kt++) {
        if (kt + 1 < 16) cp_wait<1>(); else cp_wait<0>();
        __syncthreads();
        if (kt + 2 < 16) issue(kt + 2, (kt + 2) % 3);
        compute(kt % 3);
    }

    // ---- staged epilogue: smem transpose, then coalesced uint4 stores ----
    __half* stg = &As[0][0][0];
    const int t = m0 >> 9;             // 0=q, 1=k, 2=v
    const int h0 = (m0 >> 6) & 7;
    __syncthreads();                   // protect smem from in-flight ldsm
    if (t < 2) {
        const float QSC = 0.125f * 1.4426950408889634f;
        float sc = (t == 0) ? QSC : 1.f;
        EPI_BEGIN
            stg[(col - n0) * 136 + (row - m0)] = __float2half_rn(v * sc);
        EPI_END
    } else {
        EPI_BEGIN
            stg[(row - m0) * 72 + (col - n0)] = __float2half_rn(v);
        EPI_END
    }
    __syncthreads();
    if (t < 2) {
        __half* dbase = (t == 0) ? g_qh : g_kh;
        int nl = tid >> 2, sub = tid & 3;       // nl 0..63, sub 0..3
        int ol = sub * 32;                      // 0,32,64,96
        int bh = b * 8 + h0 + (ol >> 6);
        int d0 = ol & 63;
        const uint4* src = (const uint4*)&stg[nl * 136 + ol];
        uint4* dst = (uint4*)&dbase[((size_t)bh * NSP + n0 + nl) * 64 + d0];
        #pragma unroll
        for (int i = 0; i < 4; i++) dst[i] = src[i];
    } else {
        int ol = tid >> 1, hf = tid & 1;        // ol 0..127
        int bh = b * 8 + h0 + (ol >> 6);
        int d = ol & 63;
        const uint4* src = (const uint4*)&stg[ol * 72 + hf * 32];
        uint4* dst = (uint4*)&g_vth[((size_t)bh * DH_ + d) * 1024 + n0 + hf * 32];
        #pragma unroll
        for (int i = 0; i < 4; i++) dst[i] = src[i];
    }
}

// ---------------- fused flash attention (128-row Q, staged epilogue) ---------
#define FSTR 72
#define FLASH_SMEM ((128 + 192 + 192) * FSTR * 2)

__global__ __launch_bounds__(256, 2) void k_flash(void)
{
    extern __shared__ __half fs[];
    __half* Qs = fs;                       // [128][FSTR]
    __half* Ks = fs + 128 * FSTR;          // [3][64][FSTR]
    __half* Vs = Ks + 3 * 64 * FSTR;       // [3][64][FSTR], rows = d

    const int tid = threadIdx.x, lane = tid & 31, warp = tid >> 5;
    const int bh = blockIdx.y, q0 = blockIdx.x * 128;
    const int b = bh >> 3, h = bh & 7;
    const __half* gq = g_qh + (size_t)bh * NSP * 64;
    const __half* gk = g_kh + (size_t)bh * NSP * 64;
    const __half* gv = g_vth + (size_t)bh * DH_ * 1024;
    const int la = lane & 15, ha = (lane >> 4) * 8;
    const int lbr = (lane & 7) + ((lane >> 4) & 1) * 8;
    const int lbc = ((lane >> 3) & 1) * 8;

    {
        int row = tid >> 1, hf = tid & 1;
        const __half* src = gq + (size_t)(q0 + row) * 64 + hf * 32;
        __half* dst = Qs + row * FSTR + hf * 32;
        #pragma unroll
        for (int s = 0; s < 4; s++) cpa16(dst + s * 8, src + s * 8);
        cp_commit();
    }

    auto issueKV = [&](int t, int buf) {
        int kv0 = t * 64;
        int row = tid >> 2, qd = tid & 3;
        {
            __half* dst = Ks + (buf * 64 + row) * FSTR;
            const __half* src = gk + (size_t)(kv0 + row) * 64;
            cpa16(dst + qd * 16,     src + qd * 16);
            cpa16(dst + qd * 16 + 8, src + qd * 16 + 8);
        }
        {
            __half* dst = Vs + (buf * 64 + row) * FSTR;
            const __half* src = gv + (size_t)row * 1024 + kv0;
            cpa16(dst + qd * 16,     src + qd * 16);
            cpa16(dst + qd * 16 + 8, src + qd * 16 + 8);
        }
        cp_commit();
    };

    float oacc[8][4] = {};
    float l0 = 0.f, l1 = 0.f;

    issueKV(0, 0);
    issueKV(1, 1);

    for (int t = 0; t < 16; t++) {
        if (t + 1 < 16) cp_wait<1>(); else cp_wait<0>();
        __syncthreads();
        if (t + 2 < 16) issueKV(t + 2, (t + 2) % 3);

        int buf = t % 3;
        const __half* Kb = Ks + buf * 64 * FSTR;
        const __half* Vb = Vs + buf * 64 * FSTR;

        // ---- S = Q K^T ----
        float sacc[8][4] = {};
        #pragma unroll
        for (int ks = 0; ks < 4; ks++) {
            int k0 = ks * 16;
            uint32_t af[4];
            ldsm4(af, &Qs[(warp * 16 + la) * FSTR + k0 + ha]);
            #pragma unroll
            for (int jp = 0; jp < 4; jp++) {
                uint32_t bt[4];
                ldsm4(bt, &Kb[(jp * 16 + lbr) * FSTR + k0 + lbc]);
                uint32_t b0[2] = { bt[0], bt[1] }, b1[2] = { bt[2], bt[3] };
                mma16816(sacc[2 * jp], af, b0);
                mma16816(sacc[2 * jp + 1], af, b1);
            }
        }

        // ---- p = 2^sacc in fp16x2; l summed on ALU pipe (tensor is the bottleneck) ----
        uint32_t ph[8][2];
        #pragma unroll
        for (int j = 0; j < 8; j++) {
            ph[j][0] = ex2h2(cvth2(sacc[j][0], sacc[j][1]));
            ph[j][1] = ex2h2(cvth2(sacc[j][2], sacc[j][3]));
            float2 pa = __half22float2(*(__half2*)&ph[j][0]);
            float2 pb = __half22float2(*(__half2*)&ph[j][1]);
            l0 += pa.x + pa.y;
            l1 += pb.x + pb.y;
        }

        // ---- O += P V ----
        #pragma unroll
        for (int ks = 0; ks < 4; ks++) {
            int k0 = ks * 16;
            uint32_t af[4] = { ph[2 * ks][0], ph[2 * ks][1], ph[2 * ks + 1][0], ph[2 * ks + 1][1] };
            #pragma unroll
            for (int jp = 0; jp < 4; jp++) {
                uint32_t bt[4];
                ldsm4(bt, &Vb[(jp * 16 + lbr) * FSTR + k0 + lbc]);
                uint32_t b0[2] = { bt[0], bt[1] }, b1[2] = { bt[2], bt[3] };
                mma16816(oacc[2 * jp], af, b0);
                mma16816(oacc[2 * jp + 1], af, b1);
            }
        }
    }

    // ---- row-sum reduce ----
    l0 += __shfl_xor_sync(0xffffffffu, l0, 1);
    l0 += __shfl_xor_sync(0xffffffffu, l0, 2);
    l1 += __shfl_xor_sync(0xffffffffu, l1, 1);
    l1 += __shfl_xor_sync(0xffffffffu, l1, 2);
    float inv0 = 1.f / l0, inv1 = 1.f / l1;

    // ---- staged epilogue: two dense 64x64 blocks of g_oh per CTA ----
    // value (n, d): band = n&1, sp = band*512 + h*64 + d, c = n>>1
    __half* stg = Qs;   // reuse: [2 bands][64 d][64 c + 8 pad] stride 72
    __syncthreads();    // all warps done reading Qs/K/V
    #pragma unroll
    for (int j = 0; j < 8; j++)
        #pragma unroll
        for (int e = 0; e < 4; e++) {
            int n = q0 + warp * 16 + (lane >> 2) + (e >> 1) * 8;
            int d = j * 8 + 2 * (lane & 3) + (e & 1);
            float v = oacc[j][e] * ((e < 2) ? inv0 : inv1);
            int band = n & 1;
            int cl = (n - q0) >> 1;
            stg[(band * 64 + d) * 72 + cl] = __float2half_rn(v);
        }
    __syncthreads();
    {
        int band = tid >> 7, drow = (tid >> 1) & 63, hf = tid & 1;
        const uint4* src = (const uint4*)&stg[(band * 64 + drow) * 72 + hf * 32];
        uint4* dst = (uint4*)&g_oh[((size_t)b * NSP + band * 512 + h * 64 + drow) * 512
                                   + (q0 >> 1) + hf * 32];
        #pragma unroll
        for (int i = 0; i < 4; i++) dst[i] = src[i];
    }
}

// ---------------- proj GEMM (coalesced fp16 out, no transpose) ---------------
__global__ __launch_bounds__(256) void k_proj_mma(const float* __restrict__ bp,
                                                  float* __restrict__ out)
{
    int b = blockIdx.z;
    int m0 = blockIdx.y * 128;   // o
    int n0 = blockIdx.x * 64;    // sp
    float acc[2][4][4] = {};
    gemm_core(g_Wproj_h, g_oh + (size_t)b * NSP * 512, 512, m0, n0, acc);
    EPI_BEGIN
        float rr = v + bp[row];
        out[(size_t)b * 524288 + (size_t)row * NSP + col] = rr;
        g_outh[(size_t)b * 524288 + (size_t)row * NSP + col] = __float2half_rn(rr);
    EPI_END
}

// ---------------- fused att1 + att2 (trans-B read of g_outh [o][sp]) ---------
__global__ __launch_bounds__(256) void k_att12(const float* __restrict__ b1,
                                               const float* __restrict__ W2,
                                               const float* __restrict__ b2,
                                               float* __restrict__ out)
{
    __shared__ __half As[3][128][BSTR];
    __shared__ __half Bs[3][32][BSTR2];
    __shared__ float s_red[64];
    const int b = blockIdx.y;
    const int n0 = blockIdx.x * 64;    // sp
    const __half* A = g_Watt1_h;       // [128][512]
    const __half* X = g_outh + (size_t)b * 524288;   // [o=512][sp=1024]
    float acc[2][4][4] = {};

    const int tid = threadIdx.x;
    const int ln = tid & 31;
    const int wp = tid >> 5;
    const int wmq = wp >> 1, wnq = wp & 1;
    const int arow = tid >> 1, alv = (tid & 1) * 2;
    const int brow = tid >> 3, bch = tid & 7;
    const int laq = ln & 15, haq = (ln >> 4) * 8;
    const int tkr = (ln & 7) + ((ln >> 3) & 1) * 8;
    const int tnc = ((ln >> 4) & 1) * 8;

    auto issue = [&](int kt, int buf) {
        int kbase = kt * BK;
        const __half* ga = A + (size_t)arow * 512 + kbase + alv * 8;
        cpa16(&As[buf][arow][alv * 8], ga);
        cpa16(&As[buf][arow][(alv + 1) * 8], ga + 8);
        const __half* gx = X + (size_t)(kbase + brow) * NSP + n0 + bch * 8;
        cpa16(&Bs[buf][brow][bch * 8], gx);
        cp_commit();
    };

    auto compute = [&](int buf) {
        #pragma unroll
        for (int ks = 0; ks < 2; ks++) {
            int k0 = ks * 16;
            uint32_t af[2][4], bfr[4][2];
            #pragma unroll
            for (int mi = 0; mi < 2; mi++)
                ldsm4(af[mi], &As[buf][wmq * 32 + mi * 16 + laq][k0 + haq]);
            #pragma unroll
            for (int np = 0; np < 2; np++) {
                uint32_t bt[4];
                ldsm4t(bt, &Bs[buf][k0 + tkr][wnq * 32 + np * 16 + tnc]);
                bfr[2 * np][0] = bt[0]; bfr[2 * np][1] = bt[1];
                bfr[2 * np + 1][0] = bt[2]; bfr[2 * np + 1][1] = bt[3];
            }
            #pragma unroll
            for (int mi = 0; mi < 2; mi++)
                #pragma unroll
                for (int ni = 0; ni < 4; ni++)
                    mma16816(acc[mi][ni], af[mi], bfr[ni]);
        }
    };

    issue(0, 0);
    issue(1, 1);
    for (int kt = 0; kt < 16; kt++) {
        if (kt + 1 < 16) cp_wait<1>(); else cp_wait<0>();
        __syncthreads();
        if (kt + 2 < 16) issue(kt + 2, (kt + 2) % 3);
        compute(kt % 3);
    }

    if (tid < 64) s_red[tid] = 0.f;
    __syncthreads();

    {
        #pragma unroll
        for (int ni = 0; ni < 4; ni++) {
            #pragma unroll
            for (int eh = 0; eh < 2; eh++) {
                float p = 0.f;
                #pragma unroll
                for (int mi = 0; mi < 2; mi++)
                    #pragma unroll
                    for (int ev = 0; ev < 2; ev++) {
                        int row = wmq * 32 + mi * 16 + (ln >> 2) + ev * 8;
                        float hv = fmaxf(acc[mi][ni][ev * 2 + eh] + b1[row], 0.f);
                        p = fmaf(W2[row], hv, p);
                    }
                p += __shfl_xor_sync(0xffffffffu, p, 4);
                p += __shfl_xor_sync(0xffffffffu, p, 8);
                p += __shfl_xor_sync(0xffffffffu, p, 16);
                if ((ln >> 2) == 0) {
                    int cl = wnq * 32 + ni * 8 + 2 * (ln & 3) + eh;
                    atomicAdd(&s_red[cl], p);
                }
            }
        }
    }
    __syncthreads();
    if (tid < 64) {
        float a = s_red[tid] + b2[0];
        out[4194304 + b * NSP + n0 + tid] = 1.f / (1.f + __expf(-a));
    }
}

// ---------------- final scale -------------------------------------------------
__global__ void k_scale(float* __restrict__ out)
{
    int idx = blockIdx.x * 256 + threadIdx.x;
    const float* sa = out + 4194304;
    int b  = idx >> 19;
    int sp = idx & 1023;
    out[idx] *= sa[b * NSP + sp];
}

// ---------------- launch ------------------------------------------------------
extern "C" void kernel_launch(void* const* d_in, const int* in_sizes, int n_in,
                              void* d_out, int out_size)
{
    const float* x     = (const float*)d_in[0];
    const float* Wqkv  = (const float*)d_in[1];
    const float* Wproj = (const float*)d_in[2];
    const float* bproj = (const float*)d_in[3];
    const float* Watt1 = (const float*)d_in[4];
    const float* batt1 = (const float*)d_in[5];
    const float* Watt2 = (const float*)d_in[6];
    const float* batt2 = (const float*)d_in[7];
    float* out = (float*)d_out;

    __half *wqkv_h, *wproj_h, *watt1_h;
    cudaGetSymbolAddress((void**)&wqkv_h,  g_Wqkv_h);
    cudaGetSymbolAddress((void**)&wproj_h, g_Wproj_h);
    cudaGetSymbolAddress((void**)&watt1_h, g_Watt1_h);

    cudaFuncSetAttribute(k_flash, cudaFuncAttributeMaxDynamicSharedMemorySize, FLASH_SMEM);

    k_prep_w_all<<<4352, 256>>>(Wqkv, Wproj, Watt1, wqkv_h, wproj_h, watt1_h);
    k_prep_xc<<<8192, 256>>>(x);

    k_qkv_mma <<<dim3(16, 12, 8), 256>>>();
    k_flash   <<<dim3(8, 64), 256, FLASH_SMEM>>>();
    k_proj_mma<<<dim3(16, 4, 8),  256>>>(bproj, out);
    k_att12   <<<dim3(16, 8),     256>>>(batt1, Watt2, batt2, out);
    k_scale   <<<16384, 256>>>(out);
}

// round 15
// speedup vs baseline: 1.1522x; 1.0670x over previous
#include <cuda_runtime.h>
#include <cuda_fp16.h>
#include <cstdint>

// B=8, C=512, NH=8, DH=64, N=H*W=1024
#define NB   8
#define NC   512
#define NH_  8
#define DH_  64
#define NSP  1024
#define NBH  64

// ---------------- static scratch (no allocation) -----------------------------
__device__ __half g_Wqkv_h[1536 * 512];
__device__ __half g_Wproj_h[512 * 512];
__device__ __half g_Watt1_h[128 * 512];
__device__ __half g_xch[NB * NC * NSP];       // [b][c][n] fp16 (layout-preserving)
__device__ __half g_qh[NBH * NSP * 64];       // [bh][n][d], pre-scaled by 0.125*log2e
__device__ __half g_kh[NBH * NSP * 64];       // [bh][n][d]
__device__ __half g_vth[NBH * DH_ * 1024];    // [bh][d][n] (V transposed)
__device__ __half g_oh[NB * NSP * 512];       // [b][sp][c] proj input (scramble-corrected)
__device__ __half g_outh[NB * 512 * NSP];     // [b][o][sp] proj out fp16 (att1 input + final out source)

// ---------------- helpers ----------------------------------------------------
__device__ __forceinline__ void cpa16(void* s, const void* g) {
    uint32_t sa = (uint32_t)__cvta_generic_to_shared(s);
    asm volatile("cp.async.cg.shared.global [%0], [%1], 16;\n" :: "r"(sa), "l"(g) : "memory");
}
__device__ __forceinline__ void cp_commit() {
    asm volatile("cp.async.commit_group;\n" ::: "memory");
}
template<int N> __device__ __forceinline__ void cp_wait() {
    asm volatile("cp.async.wait_group %0;\n" :: "n"(N) : "memory");
}
__device__ __forceinline__ void mma16816(float c[4], const uint32_t a[4], const uint32_t b[2]) {
    asm volatile(
        "mma.sync.aligned.m16n8k16.row.col.f32.f16.f16.f32 "
        "{%0,%1,%2,%3}, {%4,%5,%6,%7}, {%8,%9}, {%0,%1,%2,%3};\n"
        : "+f"(c[0]), "+f"(c[1]), "+f"(c[2]), "+f"(c[3])
        : "r"(a[0]), "r"(a[1]), "r"(a[2]), "r"(a[3]), "r"(b[0]), "r"(b[1]));
}
__device__ __forceinline__ void ldsm4(uint32_t r[4], const void* p) {
    uint32_t sa = (uint32_t)__cvta_generic_to_shared(p);
    asm volatile("ldmatrix.sync.aligned.m8n8.x4.shared.b16 {%0,%1,%2,%3}, [%4];"
        : "=r"(r[0]), "=r"(r[1]), "=r"(r[2]), "=r"(r[3]) : "r"(sa));
}
__device__ __forceinline__ void ldsm4t(uint32_t r[4], const void* p) {
    uint32_t sa = (uint32_t)__cvta_generic_to_shared(p);
    asm volatile("ldmatrix.sync.aligned.m8n8.x4.trans.shared.b16 {%0,%1,%2,%3}, [%4];"
        : "=r"(r[0]), "=r"(r[1]), "=r"(r[2]), "=r"(r[3]) : "r"(sa));
}
__device__ __forceinline__ uint32_t cvth2(float a, float b) {
    __half2 h = __floats2half2_rn(a, b);
    return *(uint32_t*)&h;
}
__device__ __forceinline__ uint32_t ex2h2(uint32_t x) {
    uint32_t r;
    asm("ex2.approx.f16x2 %0, %1;" : "=r"(r) : "r"(x));
    return r;
}

// ---------------- 128x64 fp16 GEMM core ([n][k] B), 256 threads --------------
#define BK   32
#define BSTR 40

__device__ __forceinline__ void gemm_core(
    const __half* __restrict__ A, const __half* __restrict__ B,
    int K, int m0, int n0, float acc[2][4][4])
{
    __shared__ __half As[3][128][BSTR];
    __shared__ __half Bs[3][64][BSTR];
    const int tid = threadIdx.x;
    const int lane = tid & 31;
    const int warp = tid >> 5;
    const int wm = warp >> 1, wn = warp & 1;
    const int KT = K / BK;
    const int arow = tid >> 1, alv = (tid & 1) * 2;
    const int brow = tid >> 2, bq = tid & 3;
    const int la = lane & 15, ha = (lane >> 4) * 8;
    const int lbr = (lane & 7) + ((lane >> 4) & 1) * 8;
    const int lbc = ((lane >> 3) & 1) * 8;

    auto issue = [&](int kt, int buf) {
        int kbase = kt * BK;
        const __half* ga = A + (size_t)(m0 + arow) * K + kbase + alv * 8;
        cpa16(&As[buf][arow][alv * 8], ga);
        cpa16(&As[buf][arow][(alv + 1) * 8], ga + 8);
        const __half* gb = B + (size_t)(n0 + brow) * K + kbase + bq * 8;
        cpa16(&Bs[buf][brow][bq * 8], gb);
        cp_commit();
    };

    auto compute = [&](int buf) {
        #pragma unroll
        for (int ks = 0; ks < 2; ks++) {
            int k0 = ks * 16;
            uint32_t af[2][4], bfr[4][2];
            #pragma unroll
            for (int mi = 0; mi < 2; mi++)
                ldsm4(af[mi], &As[buf][wm * 32 + mi * 16 + la][k0 + ha]);
            #pragma unroll
            for (int np = 0; np < 2; np++) {
                uint32_t bt[4];
                ldsm4(bt, &Bs[buf][wn * 32 + np * 16 + lbr][k0 + lbc]);
                bfr[2 * np][0] = bt[0]; bfr[2 * np][1] = bt[1];
                bfr[2 * np + 1][0] = bt[2]; bfr[2 * np + 1][1] = bt[3];
            }
            #pragma unroll
            for (int mi = 0; mi < 2; mi++)
                #pragma unroll
                for (int ni = 0; ni < 4; ni++)
                    mma16816(acc[mi][ni], af[mi], bfr[ni]);
        }
    };

    issue(0, 0);
    issue(1, 1);
    for (int kt = 0; kt < KT; kt++) {
        if (kt + 1 < KT) cp_wait<1>(); else cp_wait<0>();
        __syncthreads();
        if (kt + 2 < KT) issue(kt + 2, (kt + 2) % 3);
        compute(kt % 3);
    }
}

#define EPI_BEGIN                                                     \
    const int lane = threadIdx.x & 31;                                \
    const int warp = threadIdx.x >> 5;                                \
    const int wm = warp >> 1, wn = warp & 1;                          \
    _Pragma("unroll")                                                 \
    for (int mi = 0; mi < 2; mi++)                                    \
    _Pragma("unroll")                                                 \
    for (int ni = 0; ni < 4; ni++)                                    \
    _Pragma("unroll")                                                 \
    for (int e = 0; e < 4; e++) {                                     \
        int row = m0 + wm * 32 + mi * 16 + (lane >> 2) + ((e >> 1) * 8); \
        int col = n0 + wn * 32 + ni * 8 + 2 * (lane & 3) + (e & 1);   \
        float v = acc[mi][ni][e];
#define EPI_END }

// ---------------- merged prep: weights + x convert ---------------------------
__global__ void k_prep_all(const float* __restrict__ x,
                           const float* __restrict__ Wqkv, const float* __restrict__ Wproj,
                           const float* __restrict__ Watt1,
                           __half* __restrict__ q_h, __half* __restrict__ p_h,
                           __half* __restrict__ a_h)
{
    int i = blockIdx.x * 256 + threadIdx.x;
    if (i < 2097152) {
        float2 f2 = ((const float2*)x)[i];
        ((__half2*)g_xch)[i] = __floats2half2_rn(f2.x, f2.y);
    } else {
        int j = i - 2097152;
        if (j < 786432)            q_h[j] = __float2half_rn(Wqkv[j]);
        else if (j < 1048576)      p_h[j - 786432] = __float2half_rn(Wproj[j - 786432]);
        else if (j < 1114112)      a_h[j - 1048576] = __float2half_rn(Watt1[j - 1048576]);
    }
}

// ---------------- qkv GEMM: B = x [c][n] via ldmatrix.trans, staged epi ------
#define BSTR2 72

__global__ __launch_bounds__(256) void k_qkv_mma(void)
{
    __shared__ __half As[3][128][BSTR];
    __shared__ __half Bs[3][32][BSTR2];
    const int b = blockIdx.z;
    const int m0 = blockIdx.y * 128;   // o in [0,1536), block entirely q, k, or v
    const int n0 = blockIdx.x * 64;    // n
    const __half* A = g_Wqkv_h;
    const __half* X = g_xch + (size_t)b * NC * NSP;
    float acc[2][4][4] = {};

    const int tid = threadIdx.x;
    const int ln = tid & 31;
    const int wp = tid >> 5;
    const int wmq = wp >> 1, wnq = wp & 1;
    const int arow = tid >> 1, alv = (tid & 1) * 2;
    const int brow = tid >> 3, bch = tid & 7;
    const int laq = ln & 15, haq = (ln >> 4) * 8;
    const int tkr = (ln & 7) + ((ln >> 3) & 1) * 8;
    const int tnc = ((ln >> 4) & 1) * 8;

    auto issue = [&](int kt, int buf) {
        int kbase = kt * BK;
        const __half* ga = A + (size_t)(m0 + arow) * 512 + kbase + alv * 8;
        cpa16(&As[buf][arow][alv * 8], ga);
        cpa16(&As[buf][arow][(alv + 1) * 8], ga + 8);
        const __half* gx = X + (size_t)(kbase + brow) * NSP + n0 + bch * 8;
        cpa16(&Bs[buf][brow][bch * 8], gx);
        cp_commit();
    };

    auto compute = [&](int buf) {
        #pragma unroll
        for (int ks = 0; ks < 2; ks++) {
            int k0 = ks * 16;
            uint32_t af[2][4], bfr[4][2];
            #pragma unroll
            for (int mi = 0; mi < 2; mi++)
                ldsm4(af[mi], &As[buf][wmq * 32 + mi * 16 + laq][k0 + haq]);
            #pragma unroll
            for (int np = 0; np < 2; np++) {
                uint32_t bt[4];
                ldsm4t(bt, &Bs[buf][k0 + tkr][wnq * 32 + np * 16 + tnc]);
                bfr[2 * np][0] = bt[0]; bfr[2 * np][1] = bt[1];
                bfr[2 * np + 1][0] = bt[2]; bfr[2 * np + 1][1] = bt[3];
            }
            #pragma unroll
            for (int mi = 0; mi < 2; mi++)
                #pragma unroll
                for (int ni = 0; ni < 4; ni++)
                    mma16816(acc[mi][ni], af[mi], bfr[ni]);
        }
    };

    issue(0, 0);
    issue(1, 1);
    for (int kt = 0; kt < 16; kt++) {
        if (kt + 1 < 16) cp_wait<1>(); else cp_wait<0>();
        __syncthreads();
        if (kt + 2 < 16) issue(kt + 2, (kt + 2) % 3);
        compute(kt % 3);
    }

    // ---- staged epilogue: smem transpose, then coalesced uint4 stores ----
    __half* stg = &As[0][0][0];
    const int t = m0 >> 9;             // 0=q, 1=k, 2=v
    const int h0 = (m0 >> 6) & 7;
    __syncthreads();
    if (t < 2) {
        const float QSC = 0.125f * 1.4426950408889634f;
        float sc = (t == 0) ? QSC : 1.f;
        EPI_BEGIN
            stg[(col - n0) * 136 + (row - m0)] = __float2half_rn(v * sc);
        EPI_END
    } else {
        EPI_BEGIN
            stg[(row - m0) * 72 + (col - n0)] = __float2half_rn(v);
        EPI_END
    }
    __syncthreads();
    if (t < 2) {
        __half* dbase = (t == 0) ? g_qh : g_kh;
        int nl = tid >> 2, sub = tid & 3;
        int ol = sub * 32;
        int bh = b * 8 + h0 + (ol >> 6);
        int d0 = ol & 63;
        const uint4* src = (const uint4*)&stg[nl * 136 + ol];
        uint4* dst = (uint4*)&dbase[((size_t)bh * NSP + n0 + nl) * 64 + d0];
        #pragma unroll
        for (int i = 0; i < 4; i++) dst[i] = src[i];
    } else {
        int ol = tid >> 1, hf = tid & 1;
        int bh = b * 8 + h0 + (ol >> 6);
        int d = ol & 63;
        const uint4* src = (const uint4*)&stg[ol * 72 + hf * 32];
        uint4* dst = (uint4*)&g_vth[((size_t)bh * DH_ + d) * 1024 + n0 + hf * 32];
        #pragma unroll
        for (int i = 0; i < 4; i++) dst[i] = src[i];
    }
}

// ---------------- fused flash attention (128-row Q, staged epilogue) ---------
#define FSTR 72
#define FLASH_SMEM ((128 + 192 + 192) * FSTR * 2)

__global__ __launch_bounds__(256, 2) void k_flash(void)
{
    extern __shared__ __half fs[];
    __half* Qs = fs;                       // [128][FSTR]
    __half* Ks = fs + 128 * FSTR;          // [3][64][FSTR]
    __half* Vs = Ks + 3 * 64 * FSTR;       // [3][64][FSTR], rows = d

    const int tid = threadIdx.x, lane = tid & 31, warp = tid >> 5;
    const int bh = blockIdx.y, q0 = blockIdx.x * 128;
    const int b = bh >> 3, h = bh & 7;
    const __half* gq = g_qh + (size_t)bh * NSP * 64;
    const __half* gk = g_kh + (size_t)bh * NSP * 64;
    const __half* gv = g_vth + (size_t)bh * DH_ * 1024;
    const int la = lane & 15, ha = (lane >> 4) * 8;
    const int lbr = (lane & 7) + ((lane >> 4) & 1) * 8;
    const int lbc = ((lane >> 3) & 1) * 8;

    {
        int row = tid >> 1, hf = tid & 1;
        const __half* src = gq + (size_t)(q0 + row) * 64 + hf * 32;
        __half* dst = Qs + row * FSTR + hf * 32;
        #pragma unroll
        for (int s = 0; s < 4; s++) cpa16(dst + s * 8, src + s * 8);
        cp_commit();
    }

    auto issueKV = [&](int t, int buf) {
        int kv0 = t * 64;
        int row = tid >> 2, qd = tid & 3;
        {
            __half* dst = Ks + (buf * 64 + row) * FSTR;
            const __half* src = gk + (size_t)(kv0 + row) * 64;
            cpa16(dst + qd * 16,     src + qd * 16);
            cpa16(dst + qd * 16 + 8, src + qd * 16 + 8);
        }
        {
            __half* dst = Vs + (buf * 64 + row) * FSTR;
            const __half* src = gv + (size_t)row * 1024 + kv0;
            cpa16(dst + qd * 16,     src + qd * 16);
            cpa16(dst + qd * 16 + 8, src + qd * 16 + 8);
        }
        cp_commit();
    };

    float oacc[8][4] = {};
    float l0 = 0.f, l1 = 0.f;

    issueKV(0, 0);
    issueKV(1, 1);

    for (int t = 0; t < 16; t++) {
        if (t + 1 < 16) cp_wait<1>(); else cp_wait<0>();
        __syncthreads();
        if (t + 2 < 16) issueKV(t + 2, (t + 2) % 3);

        int buf = t % 3;
        const __half* Kb = Ks + buf * 64 * FSTR;
        const __half* Vb = Vs + buf * 64 * FSTR;

        float sacc[8][4] = {};
        #pragma unroll
        for (int ks = 0; ks < 4; ks++) {
            int k0 = ks * 16;
            uint32_t af[4];
            ldsm4(af, &Qs[(warp * 16 + la) * FSTR + k0 + ha]);
            #pragma unroll
            for (int jp = 0; jp < 4; jp++) {
                uint32_t bt[4];
                ldsm4(bt, &Kb[(jp * 16 + lbr) * FSTR + k0 + lbc]);
                uint32_t b0[2] = { bt[0], bt[1] }, b1[2] = { bt[2], bt[3] };
                mma16816(sacc[2 * jp], af, b0);
                mma16816(sacc[2 * jp + 1], af, b1);
            }
        }

        uint32_t ph[8][2];
        #pragma unroll
        for (int j = 0; j < 8; j++) {
            ph[j][0] = ex2h2(cvth2(sacc[j][0], sacc[j][1]));
            ph[j][1] = ex2h2(cvth2(sacc[j][2], sacc[j][3]));
            float2 pa = __half22float2(*(__half2*)&ph[j][0]);
            float2 pb = __half22float2(*(__half2*)&ph[j][1]);
            l0 += pa.x + pa.y;
            l1 += pb.x + pb.y;
        }

        #pragma unroll
        for (int ks = 0; ks < 4; ks++) {
            int k0 = ks * 16;
            uint32_t af[4] = { ph[2 * ks][0], ph[2 * ks][1], ph[2 * ks + 1][0], ph[2 * ks + 1][1] };
            #pragma unroll
            for (int jp = 0; jp < 4; jp++) {
                uint32_t bt[4];
                ldsm4(bt, &Vb[(jp * 16 + lbr) * FSTR + k0 + lbc]);
                uint32_t b0[2] = { bt[0], bt[1] }, b1[2] = { bt[2], bt[3] };
                mma16816(oacc[2 * jp], af, b0);
                mma16816(oacc[2 * jp + 1], af, b1);
            }
        }
    }

    l0 += __shfl_xor_sync(0xffffffffu, l0, 1);
    l0 += __shfl_xor_sync(0xffffffffu, l0, 2);
    l1 += __shfl_xor_sync(0xffffffffu, l1, 1);
    l1 += __shfl_xor_sync(0xffffffffu, l1, 2);
    float inv0 = 1.f / l0, inv1 = 1.f / l1;

    __half* stg = Qs;
    __syncthreads();
    #pragma unroll
    for (int j = 0; j < 8; j++)
        #pragma unroll
        for (int e = 0; e < 4; e++) {
            int n = q0 + warp * 16 + (lane >> 2) + (e >> 1) * 8;
            int d = j * 8 + 2 * (lane & 3) + (e & 1);
            float v = oacc[j][e] * ((e < 2) ? inv0 : inv1);
            int band = n & 1;
            int cl = (n - q0) >> 1;
            stg[(band * 64 + d) * 72 + cl] = __float2half_rn(v);
        }
    __syncthreads();
    {
        int band = tid >> 7, drow = (tid >> 1) & 63, hf = tid & 1;
        const uint4* src = (const uint4*)&stg[(band * 64 + drow) * 72 + hf * 32];
        uint4* dst = (uint4*)&g_oh[((size_t)b * NSP + band * 512 + h * 64 + drow) * 512
                                   + (q0 >> 1) + hf * 32];
        #pragma unroll
        for (int i = 0; i < 4; i++) dst[i] = src[i];
    }
}

// ---------------- proj GEMM (fp16 out only — fp32 write deferred to k_final) -
__global__ __launch_bounds__(256) void k_proj_mma(const float* __restrict__ bp)
{
    int b = blockIdx.z;
    int m0 = blockIdx.y * 128;   // o
    int n0 = blockIdx.x * 64;    // sp
    float acc[2][4][4] = {};
    gemm_core(g_Wproj_h, g_oh + (size_t)b * NSP * 512, 512, m0, n0, acc);
    EPI_BEGIN
        g_outh[(size_t)b * 524288 + (size_t)row * NSP + col] = __float2half_rn(v + bp[row]);
    EPI_END
}

// ---------------- fused att1 + att2 (trans-B read of g_outh [o][sp]) ---------
__global__ __launch_bounds__(256) void k_att12(const float* __restrict__ b1,
                                               const float* __restrict__ W2,
                                               const float* __restrict__ b2,
                                               float* __restrict__ out)
{
    __shared__ __half As[3][128][BSTR];
    __shared__ __half Bs[3][32][BSTR2];
    __shared__ float s_red[64];
    const int b = blockIdx.y;
    const int n0 = blockIdx.x * 64;    // sp
    const __half* A = g_Watt1_h;       // [128][512]
    const __half* X = g_outh + (size_t)b * 524288;   // [o=512][sp=1024]
    float acc[2][4][4] = {};

    const int tid = threadIdx.x;
    const int ln = tid & 31;
    const int wp = tid >> 5;
    const int wmq = wp >> 1, wnq = wp & 1;
    const int arow = tid >> 1, alv = (tid & 1) * 2;
    const int brow = tid >> 3, bch = tid & 7;
    const int laq = ln & 15, haq = (ln >> 4) * 8;
    const int tkr = (ln & 7) + ((ln >> 3) & 1) * 8;
    const int tnc = ((ln >> 4) & 1) * 8;

    auto issue = [&](int kt, int buf) {
        int kbase = kt * BK;
        const __half* ga = A + (size_t)arow * 512 + kbase + alv * 8;
        cpa16(&As[buf][arow][alv * 8], ga);
        cpa16(&As[buf][arow][(alv + 1) * 8], ga + 8);
        const __half* gx = X + (size_t)(kbase + brow) * NSP + n0 + bch * 8;
        cpa16(&Bs[buf][brow][bch * 8], gx);
        cp_commit();
    };

    auto compute = [&](int buf) {
        #pragma unroll
        for (int ks = 0; ks < 2; ks++) {
            int k0 = ks * 16;
            uint32_t af[2][4], bfr[4][2];
            #pragma unroll
            for (int mi = 0; mi < 2; mi++)
                ldsm4(af[mi], &As[buf][wmq * 32 + mi * 16 + laq][k0 + haq]);
            #pragma unroll
            for (int np = 0; np < 2; np++) {
                uint32_t bt[4];
                ldsm4t(bt, &Bs[buf][k0 + tkr][wnq * 32 + np * 16 + tnc]);
                bfr[2 * np][0] = bt[0]; bfr[2 * np][1] = bt[1];
                bfr[2 * np + 1][0] = bt[2]; bfr[2 * np + 1][1] = bt[3];
            }
            #pragma unroll
            for (int mi = 0; mi < 2; mi++)
                #pragma unroll
                for (int ni = 0; ni < 4; ni++)
                    mma16816(acc[mi][ni], af[mi], bfr[ni]);
        }
    };

    issue(0, 0);
    issue(1, 1);
    for (int kt = 0; kt < 16; kt++) {
        if (kt + 1 < 16) cp_wait<1>(); else cp_wait<0>();
        __syncthreads();
        if (kt + 2 < 16) issue(kt + 2, (kt + 2) % 3);
        compute(kt % 3);
    }

    if (tid < 64) s_red[tid] = 0.f;
    __syncthreads();

    {
        #pragma unroll
        for (int ni = 0; ni < 4; ni++) {
            #pragma unroll
            for (int eh = 0; eh < 2; eh++) {
                float p = 0.f;
                #pragma unroll
                for (int mi = 0; mi < 2; mi++)
                    #pragma unroll
                    for (int ev = 0; ev < 2; ev++) {
                        int row = wmq * 32 + mi * 16 + (ln >> 2) + ev * 8;
                        float hv = fmaxf(acc[mi][ni][ev * 2 + eh] + b1[row], 0.f);
                        p = fmaf(W2[row], hv, p);
                    }
                p += __shfl_xor_sync(0xffffffffu, p, 4);
                p += __shfl_xor_sync(0xffffffffu, p, 8);
                p += __shfl_xor_sync(0xffffffffu, p, 16);
                if ((ln >> 2) == 0) {
                    int cl = wnq * 32 + ni * 8 + 2 * (ln & 3) + eh;
                    atomicAdd(&s_red[cl], p);
                }
            }
        }
    }
    __syncthreads();
    if (tid < 64) {
        float a = s_red[tid] + b2[0];
        out[4194304 + b * NSP + n0 + tid] = 1.f / (1.f + __expf(-a));
    }
}

// ---------------- final: out = float(g_outh) * spatial_att -------------------
__global__ void k_final(float* __restrict__ out)
{
    int i = blockIdx.x * 256 + threadIdx.x;     // over half2 elements (2.1M)
    const float* sa = out + 4194304;
    int b  = i >> 18;           // / 262144 (half2 per batch)
    int sp2 = i & 511;          // half2 index within row -> sp = 2*sp2
    __half2 h2 = ((const __half2*)g_outh)[i];
    float2 f2 = __half22float2(h2);
    int spb = b * NSP + sp2 * 2;
    f2.x *= sa[spb];
    f2.y *= sa[spb + 1];
    ((float2*)out)[i] = f2;
}

// ---------------- launch ------------------------------------------------------
extern "C" void kernel_launch(void* const* d_in, const int* in_sizes, int n_in,
                              void* d_out, int out_size)
{
    const float* x     = (const float*)d_in[0];
    const float* Wqkv  = (const float*)d_in[1];
    const float* Wproj = (const float*)d_in[2];
    const float* bproj = (const float*)d_in[3];
    const float* Watt1 = (const float*)d_in[4];
    const float* batt1 = (const float*)d_in[5];
    const float* Watt2 = (const float*)d_in[6];
    const float* batt2 = (const float*)d_in[7];
    float* out = (float*)d_out;

    __half *wqkv_h, *wproj_h, *watt1_h;
    cudaGetSymbolAddress((void**)&wqkv_h,  g_Wqkv_h);
    cudaGetSymbolAddress((void**)&wproj_h, g_Wproj_h);
    cudaGetSymbolAddress((void**)&watt1_h, g_Watt1_h);

    cudaFuncSetAttribute(k_flash, cudaFuncAttributeMaxDynamicSharedMemorySize, FLASH_SMEM);

    k_prep_all<<<12544, 256>>>(x, Wqkv, Wproj, Watt1, wqkv_h, wproj_h, watt1_h);

    k_qkv_mma <<<dim3(16, 12, 8), 256>>>();
    k_flash   <<<dim3(8, 64), 256, FLASH_SMEM>>>();
    k_proj_mma<<<dim3(16, 4, 8),  256>>>(bproj);
    k_att12   <<<dim3(16, 8),     256>>>(batt1, Watt2, batt2, out);
    k_final   <<<8192, 256>>>(out);
}

// round 16
// speedup vs baseline: 1.1549x; 1.0024x over previous
#include <cuda_runtime.h>
#include <cuda_fp16.h>
#include <cstdint>

// B=8, C=512, NH=8, DH=64, N=H*W=1024
#define NB   8
#define NC   512
#define NH_  8
#define DH_  64
#define NSP  1024
#define NBH  64

// ---------------- static scratch (no allocation) -----------------------------
__device__ __half g_Wqkv_h[1536 * 512];
__device__ __half g_Wproj_h[512 * 512];
__device__ __half g_Watt1_h[128 * 512];
__device__ __half g_xch[NB * NC * NSP];       // [b][c][n] fp16 (layout-preserving)
__device__ __half g_qh[NBH * NSP * 64];       // [bh][n][d], pre-scaled by 0.125*log2e
__device__ __half g_kh[NBH * NSP * 64];       // [bh][n][d]
__device__ __half g_vth[NBH * DH_ * 1024];    // [bh][d][n] (V transposed)
__device__ __half g_oh[NB * NSP * 512];       // [b][sp][c] proj input (scramble-corrected)
__device__ __half g_outh[NB * 512 * NSP];     // [b][o][sp] proj out fp16

// ---------------- helpers ----------------------------------------------------
__device__ __forceinline__ void cpa16(void* s, const void* g) {
    uint32_t sa = (uint32_t)__cvta_generic_to_shared(s);
    asm volatile("cp.async.cg.shared.global [%0], [%1], 16;\n" :: "r"(sa), "l"(g) : "memory");
}
__device__ __forceinline__ void cp_commit() {
    asm volatile("cp.async.commit_group;\n" ::: "memory");
}
template<int N> __device__ __forceinline__ void cp_wait() {
    asm volatile("cp.async.wait_group %0;\n" :: "n"(N) : "memory");
}
__device__ __forceinline__ void mma16816(float c[4], const uint32_t a[4], const uint32_t b[2]) {
    asm volatile(
        "mma.sync.aligned.m16n8k16.row.col.f32.f16.f16.f32 "
        "{%0,%1,%2,%3}, {%4,%5,%6,%7}, {%8,%9}, {%0,%1,%2,%3};\n"
        : "+f"(c[0]), "+f"(c[1]), "+f"(c[2]), "+f"(c[3])
        : "r"(a[0]), "r"(a[1]), "r"(a[2]), "r"(a[3]), "r"(b[0]), "r"(b[1]));
}
__device__ __forceinline__ void ldsm4(uint32_t r[4], const void* p) {
    uint32_t sa = (uint32_t)__cvta_generic_to_shared(p);
    asm volatile("ldmatrix.sync.aligned.m8n8.x4.shared.b16 {%0,%1,%2,%3}, [%4];"
        : "=r"(r[0]), "=r"(r[1]), "=r"(r[2]), "=r"(r[3]) : "r"(sa));
}
__device__ __forceinline__ void ldsm4t(uint32_t r[4], const void* p) {
    uint32_t sa = (uint32_t)__cvta_generic_to_shared(p);
    asm volatile("ldmatrix.sync.aligned.m8n8.x4.trans.shared.b16 {%0,%1,%2,%3}, [%4];"
        : "=r"(r[0]), "=r"(r[1]), "=r"(r[2]), "=r"(r[3]) : "r"(sa));
}
__device__ __forceinline__ uint32_t cvth2(float a, float b) {
    __half2 h = __floats2half2_rn(a, b);
    return *(uint32_t*)&h;
}
__device__ __forceinline__ uint32_t ex2h2(uint32_t x) {
    uint32_t r;
    asm("ex2.approx.f16x2 %0, %1;" : "=r"(r) : "r"(x));
    return r;
}

#define BK    32
#define BSTR  40
#define BSTR2 72

// ---------------- merged prep: weights + x convert ---------------------------
__global__ void k_prep_all(const float* __restrict__ x,
                           const float* __restrict__ Wqkv, const float* __restrict__ Wproj,
                           const float* __restrict__ Watt1,
                           __half* __restrict__ q_h, __half* __restrict__ p_h,
                           __half* __restrict__ a_h)
{
    int i = blockIdx.x * 256 + threadIdx.x;
    if (i < 2097152) {
        float2 f2 = ((const float2*)x)[i];
        ((__half2*)g_xch)[i] = __floats2half2_rn(f2.x, f2.y);
    } else {
        int j = i - 2097152;
        if (j < 786432)            q_h[j] = __float2half_rn(Wqkv[j]);
        else if (j < 1048576)      p_h[j - 786432] = __float2half_rn(Wproj[j - 786432]);
        else if (j < 1114112)      a_h[j - 1048576] = __float2half_rn(Watt1[j - 1048576]);
    }
}

// ---------------- qkv GEMM: B = x [c][n] via ldmatrix.trans, staged epi ------
__global__ __launch_bounds__(256) void k_qkv_mma(void)
{
    __shared__ __half As[3][128][BSTR];
    __shared__ __half Bs[3][32][BSTR2];
    const int b = blockIdx.z;
    const int m0 = blockIdx.y * 128;
    const int n0 = blockIdx.x * 64;
    const __half* A = g_Wqkv_h;
    const __half* X = g_xch + (size_t)b * NC * NSP;
    float acc[2][4][4] = {};

    const int tid = threadIdx.x;
    const int ln = tid & 31;
    const int wp = tid >> 5;
    const int wmq = wp >> 1, wnq = wp & 1;
    const int arow = tid >> 1, alv = (tid & 1) * 2;
    const int brow = tid >> 3, bch = tid & 7;
    const int laq = ln & 15, haq = (ln >> 4) * 8;
    const int tkr = (ln & 7) + ((ln >> 3) & 1) * 8;
    const int tnc = ((ln >> 4) & 1) * 8;

    auto issue = [&](int kt, int buf) {
        int kbase = kt * BK;
        const __half* ga = A + (size_t)(m0 + arow) * 512 + kbase + alv * 8;
        cpa16(&As[buf][arow][alv * 8], ga);
        cpa16(&As[buf][arow][(alv + 1) * 8], ga + 8);
        const __half* gx = X + (size_t)(kbase + brow) * NSP + n0 + bch * 8;
        cpa16(&Bs[buf][brow][bch * 8], gx);
        cp_commit();
    };

    auto compute = [&](int buf) {
        #pragma unroll
        for (int ks = 0; ks < 2; ks++) {
            int k0 = ks * 16;
            uint32_t af[2][4], bfr[4][2];
            #pragma unroll
            for (int mi = 0; mi < 2; mi++)
                ldsm4(af[mi], &As[buf][wmq * 32 + mi * 16 + laq][k0 + haq]);
            #pragma unroll
            for (int np = 0; np < 2; np++) {
                uint32_t bt[4];
                ldsm4t(bt, &Bs[buf][k0 + tkr][wnq * 32 + np * 16 + tnc]);
                bfr[2 * np][0] = bt[0]; bfr[2 * np][1] = bt[1];
                bfr[2 * np + 1][0] = bt[2]; bfr[2 * np + 1][1] = bt[3];
            }
            #pragma unroll
            for (int mi = 0; mi < 2; mi++)
                #pragma unroll
                for (int ni = 0; ni < 4; ni++)
                    mma16816(acc[mi][ni], af[mi], bfr[ni]);
        }
    };

    issue(0, 0);
    issue(1, 1);
    for (int kt = 0; kt < 16; kt++) {
        if (kt + 1 < 16) cp_wait<1>(); else cp_wait<0>();
        __syncthreads();
        if (kt + 2 < 16) issue(kt + 2, (kt + 2) % 3);
        compute(kt % 3);
    }

    __half* stg = &As[0][0][0];
    const int t = m0 >> 9;
    const int h0 = (m0 >> 6) & 7;
    __syncthreads();
    if (t < 2) {
        const float QSC = 0.125f * 1.4426950408889634f;
        float sc = (t == 0) ? QSC : 1.f;
        #pragma unroll
        for (int mi = 0; mi < 2; mi++)
            #pragma unroll
            for (int ni = 0; ni < 4; ni++)
                #pragma unroll
                for (int e = 0; e < 4; e++) {
                    int row = wmq * 32 + mi * 16 + (ln >> 2) + (e >> 1) * 8;
                    int col = wnq * 32 + ni * 8 + 2 * (ln & 3) + (e & 1);
                    stg[col * 136 + row] = __float2half_rn(acc[mi][ni][e] * sc);
                }
    } else {
        #pragma unroll
        for (int mi = 0; mi < 2; mi++)
            #pragma unroll
            for (int ni = 0; ni < 4; ni++)
                #pragma unroll
                for (int e = 0; e < 4; e++) {
                    int row = wmq * 32 + mi * 16 + (ln >> 2) + (e >> 1) * 8;
                    int col = wnq * 32 + ni * 8 + 2 * (ln & 3) + (e & 1);
                    stg[row * 72 + col] = __float2half_rn(acc[mi][ni][e]);
                }
    }
    __syncthreads();
    if (t < 2) {
        __half* dbase = (t == 0) ? g_qh : g_kh;
        int nl = tid >> 2, sub = tid & 3;
        int ol = sub * 32;
        int bh = b * 8 + h0 + (ol >> 6);
        int d0 = ol & 63;
        const uint4* src = (const uint4*)&stg[nl * 136 + ol];
        uint4* dst = (uint4*)&dbase[((size_t)bh * NSP + n0 + nl) * 64 + d0];
        #pragma unroll
        for (int i = 0; i < 4; i++) dst[i] = src[i];
    } else {
        int ol = tid >> 1, hf = tid & 1;
        int bh = b * 8 + h0 + (ol >> 6);
        int d = ol & 63;
        const uint4* src = (const uint4*)&stg[ol * 72 + hf * 32];
        uint4* dst = (uint4*)&g_vth[((size_t)bh * DH_ + d) * 1024 + n0 + hf * 32];
        #pragma unroll
        for (int i = 0; i < 4; i++) dst[i] = src[i];
    }
}

// ---------------- fused flash attention (128-row Q, staged epilogue) ---------
#define FSTR 72
#define FLASH_SMEM ((128 + 192 + 192) * FSTR * 2)

__global__ __launch_bounds__(256, 2) void k_flash(void)
{
    extern __shared__ __half fs[];
    __half* Qs = fs;
    __half* Ks = fs + 128 * FSTR;
    __half* Vs = Ks + 3 * 64 * FSTR;

    const int tid = threadIdx.x, lane = tid & 31, warp = tid >> 5;
    const int bh = blockIdx.y, q0 = blockIdx.x * 128;
    const int b = bh >> 3, h = bh & 7;
    const __half* gq = g_qh + (size_t)bh * NSP * 64;
    const __half* gk = g_kh + (size_t)bh * NSP * 64;
    const __half* gv = g_vth + (size_t)bh * DH_ * 1024;
    const int la = lane & 15, ha = (lane >> 4) * 8;
    const int lbr = (lane & 7) + ((lane >> 4) & 1) * 8;
    const int lbc = ((lane >> 3) & 1) * 8;

    {
        int row = tid >> 1, hf = tid & 1;
        const __half* src = gq + (size_t)(q0 + row) * 64 + hf * 32;
        __half* dst = Qs + row * FSTR + hf * 32;
        #pragma unroll
        for (int s = 0; s < 4; s++) cpa16(dst + s * 8, src + s * 8);
        cp_commit();
    }

    auto issueKV = [&](int t, int buf) {
        int kv0 = t * 64;
        int row = tid >> 2, qd = tid & 3;
        {
            __half* dst = Ks + (buf * 64 + row) * FSTR;
            const __half* src = gk + (size_t)(kv0 + row) * 64;
            cpa16(dst + qd * 16,     src + qd * 16);
            cpa16(dst + qd * 16 + 8, src + qd * 16 + 8);
        }
        {
            __half* dst = Vs + (buf * 64 + row) * FSTR;
            const __half* src = gv + (size_t)row * 1024 + kv0;
            cpa16(dst + qd * 16,     src + qd * 16);
            cpa16(dst + qd * 16 + 8, src + qd * 16 + 8);
        }
        cp_commit();
    };

    float oacc[8][4] = {};
    float l0 = 0.f, l1 = 0.f;

    issueKV(0, 0);
    issueKV(1, 1);

    for (int t = 0; t < 16; t++) {
        if (t + 1 < 16) cp_wait<1>(); else cp_wait<0>();
        __syncthreads();
        if (t + 2 < 16) issueKV(t + 2, (t + 2) % 3);

        int buf = t % 3;
        const __half* Kb = Ks + buf * 64 * FSTR;
        const __half* Vb = Vs + buf * 64 * FSTR;

        float sacc[8][4] = {};
        #pragma unroll
        for (int ks = 0; ks < 4; ks++) {
            int k0 = ks * 16;
            uint32_t af[4];
            ldsm4(af, &Qs[(warp * 16 + la) * FSTR + k0 + ha]);
            #pragma unroll
            for (int jp = 0; jp < 4; jp++) {
                uint32_t bt[4];
                ldsm4(bt, &Kb[(jp * 16 + lbr) * FSTR + k0 + lbc]);
                uint32_t b0[2] = { bt[0], bt[1] }, b1[2] = { bt[2], bt[3] };
                mma16816(sacc[2 * jp], af, b0);
                mma16816(sacc[2 * jp + 1], af, b1);
            }
        }

        uint32_t ph[8][2];
        #pragma unroll
        for (int j = 0; j < 8; j++) {
            ph[j][0] = ex2h2(cvth2(sacc[j][0], sacc[j][1]));
            ph[j][1] = ex2h2(cvth2(sacc[j][2], sacc[j][3]));
            float2 pa = __half22float2(*(__half2*)&ph[j][0]);
            float2 pb = __half22float2(*(__half2*)&ph[j][1]);
            l0 += pa.x + pa.y;
            l1 += pb.x + pb.y;
        }

        #pragma unroll
        for (int ks = 0; ks < 4; ks++) {
            int k0 = ks * 16;
            uint32_t af[4] = { ph[2 * ks][0], ph[2 * ks][1], ph[2 * ks + 1][0], ph[2 * ks + 1][1] };
            #pragma unroll
            for (int jp = 0; jp < 4; jp++) {
                uint32_t bt[4];
                ldsm4(bt, &Vb[(jp * 16 + lbr) * FSTR + k0 + lbc]);
                uint32_t b0[2] = { bt[0], bt[1] }, b1[2] = { bt[2], bt[3] };
                mma16816(oacc[2 * jp], af, b0);
                mma16816(oacc[2 * jp + 1], af, b1);
            }
        }
    }

    l0 += __shfl_xor_sync(0xffffffffu, l0, 1);
    l0 += __shfl_xor_sync(0xffffffffu, l0, 2);
    l1 += __shfl_xor_sync(0xffffffffu, l1, 1);
    l1 += __shfl_xor_sync(0xffffffffu, l1, 2);
    float inv0 = 1.f / l0, inv1 = 1.f / l1;

    __half* stg = Qs;
    __syncthreads();
    #pragma unroll
    for (int j = 0; j < 8; j++)
        #pragma unroll
        for (int e = 0; e < 4; e++) {
            int n = q0 + warp * 16 + (lane >> 2) + (e >> 1) * 8;
            int d = j * 8 + 2 * (lane & 3) + (e & 1);
            float v = oacc[j][e] * ((e < 2) ? inv0 : inv1);
            int band = n & 1;
            int cl = (n - q0) >> 1;
            stg[(band * 64 + d) * 72 + cl] = __float2half_rn(v);
        }
    __syncthreads();
    {
        int band = tid >> 7, drow = (tid >> 1) & 63, hf = tid & 1;
        const uint4* src = (const uint4*)&stg[(band * 64 + drow) * 72 + hf * 32];
        uint4* dst = (uint4*)&g_oh[((size_t)b * NSP + band * 512 + h * 64 + drow) * 512
                                   + (q0 >> 1) + hf * 32];
        #pragma unroll
        for (int i = 0; i < 4; i++) dst[i] = src[i];
    }
}

// ---------------- proj GEMM: 128x128 tile, symmetric K-major A/B -------------
#define PROJ_SMEM (3 * (128 * BSTR + 128 * BSTR) * 2)

__global__ __launch_bounds__(256, 2) void k_proj_mma(const float* __restrict__ bp)
{
    extern __shared__ __half ds[];
    __half (*As)[128][BSTR] = (__half(*)[128][BSTR])ds;
    __half (*Bs)[128][BSTR] = (__half(*)[128][BSTR])(ds + 3 * 128 * BSTR);
    const int b = blockIdx.z;
    const int m0 = blockIdx.y * 128;   // o
    const int n0 = blockIdx.x * 128;   // sp
    const __half* A = g_Wproj_h;
    const __half* Bm = g_oh + (size_t)b * NSP * 512;
    float acc[2][8][4] = {};

    const int tid = threadIdx.x;
    const int lane = tid & 31;
    const int warp = tid >> 5;
    const int wm = warp >> 1, wn = warp & 1;   // wm 0..3, wn 0..1 (64 n each)
    const int arow = tid >> 1, alv = (tid & 1) * 2;
    const int la = lane & 15, ha = (lane >> 4) * 8;
    const int lbr = (lane & 7) + ((lane >> 4) & 1) * 8;
    const int lbc = ((lane >> 3) & 1) * 8;

    auto issue = [&](int kt, int buf) {
        int kbase = kt * BK;
        const __half* ga = A + (size_t)(m0 + arow) * 512 + kbase + alv * 8;
        cpa16(&As[buf][arow][alv * 8], ga);
        cpa16(&As[buf][arow][(alv + 1) * 8], ga + 8);
        const __half* gb = Bm + (size_t)(n0 + arow) * 512 + kbase + alv * 8;
        cpa16(&Bs[buf][arow][alv * 8], gb);
        cpa16(&Bs[buf][arow][(alv + 1) * 8], gb + 8);
        cp_commit();
    };

    auto compute = [&](int buf) {
        #pragma unroll
        for (int ks = 0; ks < 2; ks++) {
            int k0 = ks * 16;
            uint32_t af[2][4], bfr[8][2];
            #pragma unroll
            for (int mi = 0; mi < 2; mi++)
                ldsm4(af[mi], &As[buf][wm * 32 + mi * 16 + la][k0 + ha]);
            #pragma unroll
            for (int np = 0; np < 4; np++) {
                uint32_t bt[4];
                ldsm4(bt, &Bs[buf][wn * 64 + np * 16 + lbr][k0 + lbc]);
                bfr[2 * np][0] = bt[0]; bfr[2 * np][1] = bt[1];
                bfr[2 * np + 1][0] = bt[2]; bfr[2 * np + 1][1] = bt[3];
            }
            #pragma unroll
            for (int mi = 0; mi < 2; mi++)
                #pragma unroll
                for (int ni = 0; ni < 8; ni++)
                    mma16816(acc[mi][ni], af[mi], bfr[ni]);
        }
    };

    issue(0, 0);
    issue(1, 1);
    for (int kt = 0; kt < 16; kt++) {
        if (kt + 1 < 16) cp_wait<1>(); else cp_wait<0>();
        __syncthreads();
        if (kt + 2 < 16) issue(kt + 2, (kt + 2) % 3);
        compute(kt % 3);
    }

    #pragma unroll
    for (int mi = 0; mi < 2; mi++)
        #pragma unroll
        for (int ni = 0; ni < 8; ni++)
            #pragma unroll
            for (int e = 0; e < 4; e++) {
                int row = m0 + wm * 32 + mi * 16 + (lane >> 2) + (e >> 1) * 8;
                int col = n0 + wn * 64 + ni * 8 + 2 * (lane & 3) + (e & 1);
                g_outh[(size_t)b * 524288 + (size_t)row * NSP + col] =
                    __float2half_rn(acc[mi][ni][e] + bp[row]);
            }
}

// ---------------- fused att1 + att2: 128x128 tile, trans-B -------------------
#define ATT_SMEM (3 * 128 * BSTR * 2 + 3 * 32 * 136 * 2 + 128 * 4)

__global__ __launch_bounds__(256, 2) void k_att12(const float* __restrict__ b1,
                                                  const float* __restrict__ W2,
                                                  const float* __restrict__ b2,
                                                  float* __restrict__ out)
{
    extern __shared__ __half ds[];
    __half (*As)[128][BSTR] = (__half(*)[128][BSTR])ds;
    __half (*Bs)[32][136]   = (__half(*)[32][136])(ds + 3 * 128 * BSTR);
    float* s_red = (float*)(ds + 3 * 128 * BSTR + 3 * 32 * 136);
    const int b = blockIdx.y;
    const int n0 = blockIdx.x * 128;   // sp
    const __half* A = g_Watt1_h;       // [128][512]
    const __half* X = g_outh + (size_t)b * 524288;   // [o=512][sp=1024]
    float acc[2][8][4] = {};

    const int tid = threadIdx.x;
    const int lane = tid & 31;
    const int warp = tid >> 5;
    const int wm = warp >> 1, wn = warp & 1;
    const int arow = tid >> 1, alv = (tid & 1) * 2;
    const int brow = tid >> 3, bch = tid & 7;
    const int la = lane & 15, ha = (lane >> 4) * 8;
    const int tkr = (lane & 7) + ((lane >> 3) & 1) * 8;
    const int tnc = ((lane >> 4) & 1) * 8;

    auto issue = [&](int kt, int buf) {
        int kbase = kt * BK;
        const __half* ga = A + (size_t)arow * 512 + kbase + alv * 8;
        cpa16(&As[buf][arow][alv * 8], ga);
        cpa16(&As[buf][arow][(alv + 1) * 8], ga + 8);
        const __half* gx = X + (size_t)(kbase + brow) * NSP + n0 + bch * 16;
        cpa16(&Bs[buf][brow][bch * 16], gx);
        cpa16(&Bs[buf][brow][bch * 16 + 8], gx + 8);
        cp_commit();
    };

    auto compute = [&](int buf) {
        #pragma unroll
        for (int ks = 0; ks < 2; ks++) {
            int k0 = ks * 16;
            uint32_t af[2][4], bfr[8][2];
            #pragma unroll
            for (int mi = 0; mi < 2; mi++)
                ldsm4(af[mi], &As[buf][wm * 32 + mi * 16 + la][k0 + ha]);
            #pragma unroll
            for (int np = 0; np < 4; np++) {
                uint32_t bt[4];
                ldsm4t(bt, &Bs[buf][k0 + tkr][wn * 64 + np * 16 + tnc]);
                bfr[2 * np][0] = bt[0]; bfr[2 * np][1] = bt[1];
                bfr[2 * np + 1][0] = bt[2]; bfr[2 * np + 1][1] = bt[3];
            }
            #pragma unroll
            for (int mi = 0; mi < 2; mi++)
                #pragma unroll
                for (int ni = 0; ni < 8; ni++)
                    mma16816(acc[mi][ni], af[mi], bfr[ni]);
        }
    };

    issue(0, 0);
    issue(1, 1);
    for (int kt = 0; kt < 16; kt++) {
        if (kt + 1 < 16) cp_wait<1>(); else cp_wait<0>();
        __syncthreads();
        if (kt + 2 < 16) issue(kt + 2, (kt + 2) % 3);
        compute(kt % 3);
    }

    if (tid < 128) s_red[tid] = 0.f;
    __syncthreads();

    #pragma unroll
    for (int ni = 0; ni < 8; ni++) {
        #pragma unroll
        for (int eh = 0; eh < 2; eh++) {
            float p = 0.f;
            #pragma unroll
            for (int mi = 0; mi < 2; mi++)
                #pragma unroll
                for (int ev = 0; ev < 2; ev++) {
                    int row = wm * 32 + mi * 16 + (lane >> 2) + ev * 8;
                    float hv = fmaxf(acc[mi][ni][ev * 2 + eh] + b1[row], 0.f);
                    p = fmaf(W2[row], hv, p);
                }
            p += __shfl_xor_sync(0xffffffffu, p, 4);
            p += __shfl_xor_sync(0xffffffffu, p, 8);
            p += __shfl_xor_sync(0xffffffffu, p, 16);
            if ((lane >> 2) == 0) {
                int cl = wn * 64 + ni * 8 + 2 * (lane & 3) + eh;
                atomicAdd(&s_red[cl], p);
            }
        }
    }
    __syncthreads();
    if (tid < 128) {
        float a = s_red[tid] + b2[0];
        out[4194304 + b * NSP + n0 + tid] = 1.f / (1.f + __expf(-a));
    }
}

// ---------------- final: out = float(g_outh) * spatial_att -------------------
__global__ void k_final(float* __restrict__ out)
{
    int i = blockIdx.x * 256 + threadIdx.x;
    const float* sa = out + 4194304;
    int b  = i >> 18;
    int sp2 = i & 511;
    __half2 h2 = ((const __half2*)g_outh)[i];
    float2 f2 = __half22float2(h2);
    int spb = b * NSP + sp2 * 2;
    f2.x *= sa[spb];
    f2.y *= sa[spb + 1];
    ((float2*)out)[i] = f2;
}

// ---------------- launch ------------------------------------------------------
extern "C" void kernel_launch(void* const* d_in, const int* in_sizes, int n_in,
                              void* d_out, int out_size)
{
    const float* x     = (const float*)d_in[0];
    const float* Wqkv  = (const float*)d_in[1];
    const float* Wproj = (const float*)d_in[2];
    const float* bproj = (const float*)d_in[3];
    const float* Watt1 = (const float*)d_in[4];
    const float* batt1 = (const float*)d_in[5];
    const float* Watt2 = (const float*)d_in[6];
    const float* batt2 = (const float*)d_in[7];
    float* out = (float*)d_out;

    __half *wqkv_h, *wproj_h, *watt1_h;
    cudaGetSymbolAddress((void**)&wqkv_h,  g_Wqkv_h);
    cudaGetSymbolAddress((void**)&wproj_h, g_Wproj_h);
    cudaGetSymbolAddress((void**)&watt1_h, g_Watt1_h);

    cudaFuncSetAttribute(k_flash,    cudaFuncAttributeMaxDynamicSharedMemorySize, FLASH_SMEM);
    cudaFuncSetAttribute(k_proj_mma, cudaFuncAttributeMaxDynamicSharedMemorySize, PROJ_SMEM);
    cudaFuncSetAttribute(k_att12,    cudaFuncAttributeMaxDynamicSharedMemorySize, ATT_SMEM);

    k_prep_all<<<12544, 256>>>(x, Wqkv, Wproj, Watt1, wqkv_h, wproj_h, watt1_h);

    k_qkv_mma <<<dim3(16, 12, 8), 256>>>();
    k_flash   <<<dim3(8, 64), 256, FLASH_SMEM>>>();
    k_proj_mma<<<dim3(8, 4, 8),  256, PROJ_SMEM>>>(bproj);
    k_att12   <<<dim3(8, 8),     256, ATT_SMEM>>>(batt1, Watt2, batt2, out);
    k_final   <<<8192, 256>>>(out);
}